// round 9
// baseline (speedup 1.0000x reference)
#include <cuda_runtime.h>
#include <cuda_fp16.h>
#include <mma.h>
#include <math.h>

using namespace nvcuda;

#define N_NODES  100000
#define N_EDGES  3200000
#define N_GRAPHS 512
#define NBLK     98          // ceil(100000/1024)

// ---------------- scratch (static device globals; no allocation) ----------------
__device__ __half g_hA[(size_t)N_NODES * 256];
__device__ __half g_hB[(size_t)N_NODES * 256];
__device__ float  g_h6[(size_t)N_NODES * 64];   // final layer output (fp32 for pooling)
__device__ __half g_Wh[262144];                 // all W matrices in half (offsets below)
__device__ int    g_deg[N_NODES];
__device__ float  g_dinv[N_NODES];
__device__ int    g_rowptr[N_NODES + 1];
__device__ int    g_cursor[N_NODES];
__device__ int2   g_cw[N_EDGES];                // packed (src, weight)
__device__ int    g_bsum[128];
__device__ float  g_pool[N_GRAPHS * 64];
__device__ int    g_cnt[N_GRAPHS];

// W offsets in g_Wh (half elements)
#define OFF_W1 0           // 128*256 = 32768
#define OFF_W2 32768       // 256*256 = 65536
#define OFF_W3 98304       // 65536
#define OFF_W4 163840      // 256*128 = 32768
#define OFF_W5 196608      // 128*128 = 16384
#define OFF_W6 212992      // 128*64  = 8192

// ---------------- init ----------------
__global__ void k_init() {
    int i = blockIdx.x * blockDim.x + threadIdx.x;
    if (i < N_NODES) g_deg[i] = 1;               // self loop
    if (i < N_GRAPHS * 64) g_pool[i] = 0.f;
}

// ---------------- fp32 -> half converts ----------------
__global__ void k_tohalf(const float* __restrict__ x) {
    int i = blockIdx.x * blockDim.x + threadIdx.x;   // one float4 -> 4 halves
    if (i >= N_NODES * 32) return;
    float4 v = *(const float4*)(x + (size_t)i * 4);
    __half2 h0 = __floats2half2_rn(v.x, v.y);
    __half2 h1 = __floats2half2_rn(v.z, v.w);
    uint2 o; o.x = *(unsigned*)&h0; o.y = *(unsigned*)&h1;
    *(uint2*)(g_hA + (size_t)i * 4) = o;
}

// all six W matrices in one kernel; i indexes half2 pairs (110592 total)
__global__ void k_wconv_all(const float* __restrict__ W1, const float* __restrict__ W2,
                            const float* __restrict__ W3, const float* __restrict__ W4,
                            const float* __restrict__ W5, const float* __restrict__ W6) {
    int i = blockIdx.x * blockDim.x + threadIdx.x;
    if (i >= 110592) return;
    const float* src;
    int off, loc;
    if (i < 16384)       { src = W1; off = OFF_W1; loc = i; }
    else if (i < 49152)  { src = W2; off = OFF_W2; loc = i - 16384; }
    else if (i < 81920)  { src = W3; off = OFF_W3; loc = i - 49152; }
    else if (i < 98304)  { src = W4; off = OFF_W4; loc = i - 81920; }
    else if (i < 106496) { src = W5; off = OFF_W5; loc = i - 98304; }
    else                 { src = W6; off = OFF_W6; loc = i - 106496; }
    float2 v = *(const float2*)(src + loc * 2);
    __half2 h = __floats2half2_rn(v.x, v.y);
    *(unsigned*)(g_Wh + off + loc * 2) = *(unsigned*)&h;
}

// ---------------- degree histogram over dst ----------------
__global__ void k_hist(const int* __restrict__ dst) {
    int i = blockIdx.x * blockDim.x + threadIdx.x;
    if (i < N_EDGES) atomicAdd(&g_deg[dst[i]], 1);
}

// ---------------- 3-phase multi-block exclusive scan of (deg-1) ----------------
__global__ void k_scan1() {
    __shared__ int ws[32];
    int t = threadIdx.x;
    int i = blockIdx.x * 1024 + t;
    int v = (i < N_NODES) ? (g_deg[i] - 1) : 0;
    int lane = t & 31, wid = t >> 5;
    int x = v;
#pragma unroll
    for (int off = 1; off < 32; off <<= 1) {
        int y = __shfl_up_sync(0xffffffffu, x, off);
        if (lane >= off) x += y;
    }
    if (lane == 31) ws[wid] = x;
    __syncthreads();
    if (wid == 0) {
        int s = ws[lane];
#pragma unroll
        for (int off = 1; off < 32; off <<= 1) {
            int y = __shfl_up_sync(0xffffffffu, s, off);
            if (lane >= off) s += y;
        }
        ws[lane] = s;
    }
    __syncthreads();
    int excl = (wid ? ws[wid - 1] : 0) + (x - v);
    if (i < N_NODES) g_rowptr[i] = excl;
    if (t == 0) g_bsum[blockIdx.x] = ws[31];
}

__global__ void k_scan2() {
    __shared__ int ws[4];
    int t = threadIdx.x;
    int v = (t < NBLK) ? g_bsum[t] : 0;
    int lane = t & 31, wid = t >> 5;
    int x = v;
#pragma unroll
    for (int off = 1; off < 32; off <<= 1) {
        int y = __shfl_up_sync(0xffffffffu, x, off);
        if (lane >= off) x += y;
    }
    if (lane == 31) ws[wid] = x;
    __syncthreads();
    int add = 0;
    for (int w = 0; w < wid; w++) add += ws[w];
    if (t < NBLK) g_bsum[t] = add + x - v;
}

__global__ void k_scan3() {
    int i = blockIdx.x * 1024 + threadIdx.x;
    if (i < N_NODES) {
        int v = g_rowptr[i] + g_bsum[blockIdx.x];
        g_rowptr[i] = v;
        g_cursor[i] = v;
        g_dinv[i] = rsqrtf((float)g_deg[i]);
    }
    if (i == 0) g_rowptr[N_NODES] = N_EDGES;
}

// fill CSR with packed (src, dinv[src]*dinv[dst])
__global__ void k_fill(const int* __restrict__ src, const int* __restrict__ dst) {
    int i = blockIdx.x * blockDim.x + threadIdx.x;
    if (i < N_EDGES) {
        int d = dst[i];
        int s = src[i];
        float w = g_dinv[s] * g_dinv[d];
        int p = atomicAdd(&g_cursor[d], 1);
        g_cw[p] = make_int2(s, __float_as_int(w));
    }
}

// ---------------- wmma GEMM: Out[N,Cn](half) = A[N,K](half) @ Wh[K,Cn](half) + bias, relu ----------------
__global__ __launch_bounds__(256) void k_gemm(const __half* __restrict__ A,
                                              const __half* __restrict__ W,
                                              __half* __restrict__ Out,
                                              int K, int Cn,
                                              const float* __restrict__ bias, int relu) {
    __shared__ __half As[128][24];
    __shared__ __half Ws[16][72];
    __shared__ float  stage[8][1024];

    int tid = threadIdx.x;
    int wid = tid >> 5, lane = tid & 31;
    int wr = wid & 3, wc = wid >> 2;
    int row0 = blockIdx.y * 128, col0 = blockIdx.x * 64;

    wmma::fragment<wmma::accumulator, 16, 16, 16, float> fc[2][2];
#pragma unroll
    for (int i = 0; i < 2; i++)
#pragma unroll
        for (int j = 0; j < 2; j++) wmma::fill_fragment(fc[i][j], 0.f);

    int lr = tid >> 1, lp = tid & 1;
    int grow = row0 + lr;
    bool av = grow < N_NODES;
    const __half* Ap = A + (size_t)(av ? grow : 0) * K + lp * 8;

    for (int kk = 0; kk < K; kk += 16) {
        uint4 v = make_uint4(0u, 0u, 0u, 0u);
        if (av) v = *(const uint4*)(Ap + kk);
        *(uint4*)&As[lr][lp * 8] = v;
        if (tid < 128) {
            int r = tid >> 3, p = tid & 7;
            *(uint4*)&Ws[r][p * 8] =
                *(const uint4*)(W + (size_t)(kk + r) * Cn + col0 + p * 8);
        }
        __syncthreads();
        wmma::fragment<wmma::matrix_a, 16, 16, 16, __half, wmma::row_major> fa[2];
        wmma::fragment<wmma::matrix_b, 16, 16, 16, __half, wmma::row_major> fb[2];
        wmma::load_matrix_sync(fa[0], &As[wr * 32][0], 24);
        wmma::load_matrix_sync(fa[1], &As[wr * 32 + 16][0], 24);
        wmma::load_matrix_sync(fb[0], &Ws[0][wc * 32], 72);
        wmma::load_matrix_sync(fb[1], &Ws[0][wc * 32 + 16], 72);
#pragma unroll
        for (int i = 0; i < 2; i++)
#pragma unroll
            for (int j = 0; j < 2; j++)
                wmma::mma_sync(fc[i][j], fa[i], fb[j], fc[i][j]);
        __syncthreads();
    }

#pragma unroll
    for (int i = 0; i < 2; i++)
#pragma unroll
        for (int j = 0; j < 2; j++)
            wmma::store_matrix_sync(&stage[wid][(i * 16) * 32 + j * 16], fc[i][j], 32,
                                    wmma::mem_row_major);
    __syncwarp();

    int gr = row0 + wr * 32 + lane;
    if (gr < N_NODES) {
        int gc0 = col0 + wc * 32;
        const float* srow = &stage[wid][lane * 32];
        __half* orow = Out + (size_t)gr * Cn + gc0;
#pragma unroll
        for (int q = 0; q < 4; q++) {
            float4 f0 = *(const float4*)(srow + q * 8);
            float4 f1 = *(const float4*)(srow + q * 8 + 4);
            float b[8] = {0, 0, 0, 0, 0, 0, 0, 0};
            if (bias) {
                float4 bb0 = *(const float4*)(bias + gc0 + q * 8);
                float4 bb1 = *(const float4*)(bias + gc0 + q * 8 + 4);
                b[0] = bb0.x; b[1] = bb0.y; b[2] = bb0.z; b[3] = bb0.w;
                b[4] = bb1.x; b[5] = bb1.y; b[6] = bb1.z; b[7] = bb1.w;
            }
            float r[8] = {f0.x + b[0], f0.y + b[1], f0.z + b[2], f0.w + b[3],
                          f1.x + b[4], f1.y + b[5], f1.z + b[6], f1.w + b[7]};
            if (relu) {
#pragma unroll
                for (int q2 = 0; q2 < 8; q2++) r[q2] = fmaxf(r[q2], 0.f);
            }
            __half2 h0 = __floats2half2_rn(r[0], r[1]);
            __half2 h1 = __floats2half2_rn(r[2], r[3]);
            __half2 h2 = __floats2half2_rn(r[4], r[5]);
            __half2 h3 = __floats2half2_rn(r[6], r[7]);
            uint4 o;
            o.x = *(unsigned*)&h0; o.y = *(unsigned*)&h1;
            o.z = *(unsigned*)&h2; o.w = *(unsigned*)&h3;
            *(uint4*)(orow + q * 8) = o;
        }
    }
}

// ---------------- CSR aggregation: 8-deep gather MLP + double-buffered edge fetch ----------------
template <int CW, bool OUTF>
__global__ void k_agg(const __half* __restrict__ T, void* __restrict__ Optr,
                      const float* __restrict__ bias, int relu, int stride, int choff) {
    int warp = threadIdx.x >> 5;
    int lane = threadIdx.x & 31;
    int n = blockIdx.x * 8 + warp;
    float dn = g_dinv[n];
    float dn2 = dn * dn;
    int s = g_rowptr[n], e = g_rowptr[n + 1];

    if (CW == 128) {
        int o0 = choff + lane * 4;
        uint2 raw = *(const uint2*)(T + (size_t)n * stride + o0);
        float2 f0 = __half22float2(*(__half2*)&raw.x);
        float2 f1 = __half22float2(*(__half2*)&raw.y);
        float ax = f0.x * dn2, ay = f0.y * dn2, az = f1.x * dn2, aw = f1.y * dn2;

        int2 cur = make_int2(0, 0);
        if (s + lane < e) cur = g_cw[s + lane];
        for (int base = s; base < e; base += 32) {
            int nb = base + 32;
            int2 nxt = make_int2(0, 0);
            if (nb + lane < e) nxt = g_cw[nb + lane];
            int rem = e - base;
            int nt = rem < 32 ? rem : 32;
            int t = 0;
            for (; t + 8 <= nt; t += 8) {
                int u[8]; float w[8];
#pragma unroll
                for (int k = 0; k < 8; k++) {
                    u[k] = __shfl_sync(0xffffffffu, cur.x, t + k);
                    w[k] = __int_as_float(__shfl_sync(0xffffffffu, cur.y, t + k));
                }
                uint2 r[8];
#pragma unroll
                for (int k = 0; k < 8; k++)
                    r[k] = *(const uint2*)(T + (size_t)u[k] * stride + o0);
#pragma unroll
                for (int k = 0; k < 8; k++) {
                    float2 p0 = __half22float2(*(__half2*)&r[k].x);
                    float2 p1 = __half22float2(*(__half2*)&r[k].y);
                    ax += w[k] * p0.x; ay += w[k] * p0.y;
                    az += w[k] * p1.x; aw += w[k] * p1.y;
                }
            }
            for (; t < nt; t++) {
                int u = __shfl_sync(0xffffffffu, cur.x, t);
                float w = __int_as_float(__shfl_sync(0xffffffffu, cur.y, t));
                uint2 r0 = *(const uint2*)(T + (size_t)u * stride + o0);
                float2 p0 = __half22float2(*(__half2*)&r0.x);
                float2 p1 = __half22float2(*(__half2*)&r0.y);
                ax += w * p0.x; ay += w * p0.y; az += w * p1.x; aw += w * p1.y;
            }
            cur = nxt;
        }
        float4 b0 = make_float4(0.f, 0.f, 0.f, 0.f);
        if (bias) b0 = *(const float4*)(bias + o0);
        float rx = ax + b0.x, ry = ay + b0.y, rz = az + b0.z, rw = aw + b0.w;
        if (relu) {
            rx = fmaxf(rx, 0.f); ry = fmaxf(ry, 0.f);
            rz = fmaxf(rz, 0.f); rw = fmaxf(rw, 0.f);
        }
        if (OUTF) {
            *(float4*)((float*)Optr + (size_t)n * stride + o0) = make_float4(rx, ry, rz, rw);
        } else {
            __half2 p0 = __floats2half2_rn(rx, ry);
            __half2 p1 = __floats2half2_rn(rz, rw);
            uint2 o; o.x = *(unsigned*)&p0; o.y = *(unsigned*)&p1;
            *(uint2*)((__half*)Optr + (size_t)n * stride + o0) = o;
        }
    } else { // CW == 64
        int o0 = choff + lane * 2;
        unsigned raw = *(const unsigned*)(T + (size_t)n * stride + o0);
        float2 f0 = __half22float2(*(__half2*)&raw);
        float ax = f0.x * dn2, ay = f0.y * dn2;
        int2 cur = make_int2(0, 0);
        if (s + lane < e) cur = g_cw[s + lane];
        for (int base = s; base < e; base += 32) {
            int nb = base + 32;
            int2 nxt = make_int2(0, 0);
            if (nb + lane < e) nxt = g_cw[nb + lane];
            int rem = e - base;
            int nt = rem < 32 ? rem : 32;
            int t = 0;
            for (; t + 8 <= nt; t += 8) {
                int u[8]; float w[8];
#pragma unroll
                for (int k = 0; k < 8; k++) {
                    u[k] = __shfl_sync(0xffffffffu, cur.x, t + k);
                    w[k] = __int_as_float(__shfl_sync(0xffffffffu, cur.y, t + k));
                }
                unsigned r[8];
#pragma unroll
                for (int k = 0; k < 8; k++)
                    r[k] = *(const unsigned*)(T + (size_t)u[k] * stride + o0);
#pragma unroll
                for (int k = 0; k < 8; k++) {
                    float2 p0 = __half22float2(*(__half2*)&r[k]);
                    ax += w[k] * p0.x; ay += w[k] * p0.y;
                }
            }
            for (; t < nt; t++) {
                int u = __shfl_sync(0xffffffffu, cur.x, t);
                float w = __int_as_float(__shfl_sync(0xffffffffu, cur.y, t));
                unsigned r0 = *(const unsigned*)(T + (size_t)u * stride + o0);
                float2 p0 = __half22float2(*(__half2*)&r0);
                ax += w * p0.x; ay += w * p0.y;
            }
            cur = nxt;
        }
        float2 b0 = make_float2(0.f, 0.f);
        if (bias) b0 = *(const float2*)(bias + o0);
        float rx = ax + b0.x, ry = ay + b0.y;
        if (relu) { rx = fmaxf(rx, 0.f); ry = fmaxf(ry, 0.f); }
        if (OUTF) {
            *(float2*)((float*)Optr + (size_t)n * stride + o0) = make_float2(rx, ry);
        } else {
            __half2 p0 = __floats2half2_rn(rx, ry);
            *(unsigned*)((__half*)Optr + (size_t)n * stride + o0) = *(unsigned*)&p0;
        }
    }
}

// ---------------- pooling: run-length accumulate over 8 consecutive nodes ----------------
__global__ void k_pool(const float* __restrict__ h, const int* __restrict__ batch) {
    int idx = blockIdx.x * blockDim.x + threadIdx.x;   // (group, q): group of 8 nodes, q = channel quad
    if (idx >= (N_NODES / 8) * 16) return;
    int grp = idx >> 4, q = idx & 15;
    int n0 = grp * 8;
    float4 acc = make_float4(0.f, 0.f, 0.f, 0.f);
    int curg = batch[n0];
#pragma unroll
    for (int i = 0; i < 8; i++) {
        int n = n0 + i;
        int g = batch[n];
        float4 v = *(const float4*)(h + (size_t)n * 64 + q * 4);
        if (g != curg) {
            float* p = g_pool + curg * 64 + q * 4;
            atomicAdd(p + 0, acc.x); atomicAdd(p + 1, acc.y);
            atomicAdd(p + 2, acc.z); atomicAdd(p + 3, acc.w);
            acc = make_float4(0.f, 0.f, 0.f, 0.f);
            curg = g;
        }
        acc.x += v.x; acc.y += v.y; acc.z += v.z; acc.w += v.w;
    }
    float* p = g_pool + curg * 64 + q * 4;
    atomicAdd(p + 0, acc.x); atomicAdd(p + 1, acc.y);
    atomicAdd(p + 2, acc.z); atomicAdd(p + 3, acc.w);
}

// ---------------- counts via binary search over sorted batch ----------------
__global__ void k_cnt(const int* __restrict__ batch) {
    int g = blockIdx.x * blockDim.x + threadIdx.x;
    if (g >= N_GRAPHS) return;
    // lower_bound(batch, g)
    int lo = 0, hi = N_NODES;
    while (lo < hi) { int m = (lo + hi) >> 1; if (batch[m] < g) lo = m + 1; else hi = m; }
    int a = lo;
    lo = a; hi = N_NODES;
    while (lo < hi) { int m = (lo + hi) >> 1; if (batch[m] < g + 1) lo = m + 1; else hi = m; }
    g_cnt[g] = lo - a;
}

// ---------------- head ----------------
__global__ void k_final(const float* __restrict__ Wlin, const float* __restrict__ blin,
                        float* __restrict__ out) {
    int g = blockIdx.x;
    int t = threadIdx.x;  // 64 threads
    __shared__ float mean[64];
    __shared__ float logits[10];
    __shared__ float red2[2];
    float c = (float)g_cnt[g];
    float inv = 1.0f / fmaxf(c, 1.0f);
    mean[t] = g_pool[g * 64 + t] * inv;
    __syncthreads();
    if (t < 10) {
        float s = blin[t];
        for (int k = 0; k < 64; k++) s += mean[k] * Wlin[k * 10 + t];
        logits[t] = s;
    }
    __syncthreads();
    if (t == 0) {
        float mx = logits[0];
        for (int l = 1; l < 10; l++) mx = fmaxf(mx, logits[l]);
        float se = 0.f;
        for (int l = 0; l < 10; l++) se += expf(logits[l] - mx);
        red2[0] = mx;
        red2[1] = se;
    }
    __syncthreads();
    if (t < 10) {
        float lsm = logits[t] - red2[0] - logf(red2[1]);
        out[g * 10 + t] = lsm;
        out[N_GRAPHS * 10 + g * 10 + t] = expf(lsm);
    }
}

// ---------------- launch ----------------
extern "C" void kernel_launch(void* const* d_in, const int* in_sizes, int n_in,
                              void* d_out, int out_size) {
    const float* x     = (const float*)d_in[0];
    const int*   ei    = (const int*)d_in[1];
    const int*   batch = (const int*)d_in[2];
    const float* W1 = (const float*)d_in[4];  const float* b1 = (const float*)d_in[5];
    const float* W2 = (const float*)d_in[6];  const float* b2 = (const float*)d_in[7];
    const float* W3 = (const float*)d_in[8];  const float* b3 = (const float*)d_in[9];
    const float* W4 = (const float*)d_in[10]; const float* b4 = (const float*)d_in[11];
    const float* W5 = (const float*)d_in[12]; const float* b5 = (const float*)d_in[13];
    const float* W6 = (const float*)d_in[14]; const float* b6 = (const float*)d_in[15];
    const float* Wlin = (const float*)d_in[16];
    const float* blin = (const float*)d_in[17];
    const int* src = ei;
    const int* dst = ei + N_EDGES;
    float* out = (float*)d_out;

    __half *hA, *hB, *Wh;
    float *h6;
    cudaGetSymbolAddress((void**)&hA, g_hA);
    cudaGetSymbolAddress((void**)&hB, g_hB);
    cudaGetSymbolAddress((void**)&h6, g_h6);
    cudaGetSymbolAddress((void**)&Wh, g_Wh);

    const int TB = 256;
    int gN = (N_NODES + TB - 1) / TB;
    int gE = (N_EDGES + TB - 1) / TB;

    // preprocessing (+ converts)
    k_init<<<gN, TB>>>();
    k_tohalf<<<(N_NODES * 32 + TB - 1) / TB, TB>>>(x);
    k_wconv_all<<<(110592 + TB - 1) / TB, TB>>>(W1, W2, W3, W4, W5, W6);
    k_hist<<<gE, TB>>>(dst);
    k_scan1<<<NBLK, 1024>>>();
    k_scan2<<<1, 128>>>();
    k_scan3<<<NBLK, 1024>>>();
    k_fill<<<gE, TB>>>(src, dst);
    k_cnt<<<2, 256>>>(batch);

    int aggBlocks = N_NODES / 8;
    dim3 g256(4, 782), g128(2, 782), g64(1, 782);

    // L1: aggregate-first (128 ch) on half x, then GEMM 128->256 (+bias+relu)
    k_agg<128, false><<<aggBlocks, 256>>>(hA, hB, nullptr, 0, 128, 0);
    k_gemm<<<g256, 256>>>(hB, Wh + OFF_W1, hA, 128, 256, b1, 1);
    // L2: transform-first, split agg
    k_gemm<<<g256, 256>>>(hA, Wh + OFF_W2, hB, 256, 256, nullptr, 0);
    k_agg<128, false><<<aggBlocks, 256>>>(hB, hA, b2, 1, 256, 0);
    k_agg<128, false><<<aggBlocks, 256>>>(hB, hA, b2, 1, 256, 128);
    // L3
    k_gemm<<<g256, 256>>>(hA, Wh + OFF_W3, hB, 256, 256, nullptr, 0);
    k_agg<128, false><<<aggBlocks, 256>>>(hB, hA, b3, 1, 256, 0);
    k_agg<128, false><<<aggBlocks, 256>>>(hB, hA, b3, 1, 256, 128);
    // L4: 256->128
    k_gemm<<<g128, 256>>>(hA, Wh + OFF_W4, hB, 256, 128, nullptr, 0);
    k_agg<128, false><<<aggBlocks, 256>>>(hB, hA, b4, 1, 128, 0);
    // L5: 128->128
    k_gemm<<<g128, 256>>>(hA, Wh + OFF_W5, hB, 128, 128, nullptr, 0);
    k_agg<128, false><<<aggBlocks, 256>>>(hB, hA, b5, 1, 128, 0);
    // L6: 128->64, no relu; agg writes fp32 for pooling
    k_gemm<<<g64, 256>>>(hA, Wh + OFF_W6, hB, 128, 64, nullptr, 0);
    k_agg<64, true><<<aggBlocks, 256>>>(hB, h6, b6, 0, 64, 0);

    // pooling + head
    k_pool<<<((N_NODES / 8) * 16 + TB - 1) / TB, TB>>>(h6, batch);
    k_final<<<N_GRAPHS, 64>>>(Wlin, blin, out);
}

// round 12
// speedup vs baseline: 1.0797x; 1.0797x over previous
#include <cuda_runtime.h>
#include <cuda_fp16.h>
#include <mma.h>
#include <math.h>

using namespace nvcuda;

#define N_NODES  100000
#define N_EDGES  3200000
#define N_GRAPHS 512
#define NBLK     98          // ceil(100000/1024)

// ---------------- scratch (static device globals; no allocation) ----------------
__device__ __half g_hA[(size_t)N_NODES * 256];
__device__ __half g_hB[(size_t)N_NODES * 256];
__device__ float  g_h6[(size_t)N_NODES * 64];   // final layer output (fp32 for pooling)
__device__ __half g_Wh[262144];                 // all W matrices in half (offsets below)
__device__ int    g_deg[N_NODES];
__device__ float  g_dinv[N_NODES];
__device__ int    g_rowptr[N_NODES + 1];
__device__ int    g_cursor[N_NODES];
__device__ int2   g_cw[N_EDGES];                // packed (src, weight)
__device__ int    g_bsum[128];
__device__ float  g_pool[N_GRAPHS * 64];
__device__ int    g_cnt[N_GRAPHS];

// W offsets in g_Wh (half elements)
#define OFF_W1 0           // 128*256 = 32768
#define OFF_W2 32768       // 256*256 = 65536
#define OFF_W3 98304       // 65536
#define OFF_W4 163840      // 256*128 = 32768
#define OFF_W5 196608      // 128*128 = 16384
#define OFF_W6 212992      // 128*64  = 8192

// ---------------- init ----------------
__global__ void k_init() {
    int i = blockIdx.x * blockDim.x + threadIdx.x;
    if (i < N_NODES) g_deg[i] = 1;               // self loop
    if (i < N_GRAPHS * 64) g_pool[i] = 0.f;
}

// ---------------- fp32 -> half converts ----------------
__global__ void k_tohalf(const float* __restrict__ x) {
    int i = blockIdx.x * blockDim.x + threadIdx.x;   // one float4 -> 4 halves
    if (i >= N_NODES * 32) return;
    float4 v = *(const float4*)(x + (size_t)i * 4);
    __half2 h0 = __floats2half2_rn(v.x, v.y);
    __half2 h1 = __floats2half2_rn(v.z, v.w);
    uint2 o; o.x = *(unsigned*)&h0; o.y = *(unsigned*)&h1;
    *(uint2*)(g_hA + (size_t)i * 4) = o;
}

// all six W matrices in one kernel; i indexes half2 pairs (110592 total)
__global__ void k_wconv_all(const float* __restrict__ W1, const float* __restrict__ W2,
                            const float* __restrict__ W3, const float* __restrict__ W4,
                            const float* __restrict__ W5, const float* __restrict__ W6) {
    int i = blockIdx.x * blockDim.x + threadIdx.x;
    if (i >= 110592) return;
    const float* src;
    int off, loc;
    if (i < 16384)       { src = W1; off = OFF_W1; loc = i; }
    else if (i < 49152)  { src = W2; off = OFF_W2; loc = i - 16384; }
    else if (i < 81920)  { src = W3; off = OFF_W3; loc = i - 49152; }
    else if (i < 98304)  { src = W4; off = OFF_W4; loc = i - 81920; }
    else if (i < 106496) { src = W5; off = OFF_W5; loc = i - 98304; }
    else                 { src = W6; off = OFF_W6; loc = i - 106496; }
    float2 v = *(const float2*)(src + loc * 2);
    __half2 h = __floats2half2_rn(v.x, v.y);
    *(unsigned*)(g_Wh + off + loc * 2) = *(unsigned*)&h;
}

// ---------------- degree histogram over dst ----------------
__global__ void k_hist(const int* __restrict__ dst) {
    int i = blockIdx.x * blockDim.x + threadIdx.x;
    if (i < N_EDGES) atomicAdd(&g_deg[dst[i]], 1);
}

// ---------------- 3-phase multi-block exclusive scan of (deg-1) ----------------
__global__ void k_scan1() {
    __shared__ int ws[32];
    int t = threadIdx.x;
    int i = blockIdx.x * 1024 + t;
    int v = (i < N_NODES) ? (g_deg[i] - 1) : 0;
    int lane = t & 31, wid = t >> 5;
    int x = v;
#pragma unroll
    for (int off = 1; off < 32; off <<= 1) {
        int y = __shfl_up_sync(0xffffffffu, x, off);
        if (lane >= off) x += y;
    }
    if (lane == 31) ws[wid] = x;
    __syncthreads();
    if (wid == 0) {
        int s = ws[lane];
#pragma unroll
        for (int off = 1; off < 32; off <<= 1) {
            int y = __shfl_up_sync(0xffffffffu, s, off);
            if (lane >= off) s += y;
        }
        ws[lane] = s;
    }
    __syncthreads();
    int excl = (wid ? ws[wid - 1] : 0) + (x - v);
    if (i < N_NODES) g_rowptr[i] = excl;
    if (t == 0) g_bsum[blockIdx.x] = ws[31];
}

__global__ void k_scan2() {
    __shared__ int ws[4];
    int t = threadIdx.x;
    int v = (t < NBLK) ? g_bsum[t] : 0;
    int lane = t & 31, wid = t >> 5;
    int x = v;
#pragma unroll
    for (int off = 1; off < 32; off <<= 1) {
        int y = __shfl_up_sync(0xffffffffu, x, off);
        if (lane >= off) x += y;
    }
    if (lane == 31) ws[wid] = x;
    __syncthreads();
    int add = 0;
    for (int w = 0; w < wid; w++) add += ws[w];
    if (t < NBLK) g_bsum[t] = add + x - v;
}

__global__ void k_scan3() {
    int i = blockIdx.x * 1024 + threadIdx.x;
    if (i < N_NODES) {
        int v = g_rowptr[i] + g_bsum[blockIdx.x];
        g_rowptr[i] = v;
        g_cursor[i] = v;
        g_dinv[i] = rsqrtf((float)g_deg[i]);
    }
    if (i == 0) g_rowptr[N_NODES] = N_EDGES;
}

// fill CSR with packed (src, dinv[src]*dinv[dst])
__global__ void k_fill(const int* __restrict__ src, const int* __restrict__ dst) {
    int i = blockIdx.x * blockDim.x + threadIdx.x;
    if (i < N_EDGES) {
        int d = dst[i];
        int s = src[i];
        float w = g_dinv[s] * g_dinv[d];
        int p = atomicAdd(&g_cursor[d], 1);
        g_cw[p] = make_int2(s, __float_as_int(w));
    }
}

// ---------------- wmma GEMM: Out[N,Cn](half) = A[N,K](half) @ Wh[K,Cn](half) + bias, relu ----------------
__global__ __launch_bounds__(256) void k_gemm(const __half* __restrict__ A,
                                              const __half* __restrict__ W,
                                              __half* __restrict__ Out,
                                              int K, int Cn,
                                              const float* __restrict__ bias, int relu) {
    __shared__ __half As[128][24];
    __shared__ __half Ws[16][72];
    __shared__ float  stage[8][1024];

    int tid = threadIdx.x;
    int wid = tid >> 5, lane = tid & 31;
    int wr = wid & 3, wc = wid >> 2;
    int row0 = blockIdx.y * 128, col0 = blockIdx.x * 64;

    wmma::fragment<wmma::accumulator, 16, 16, 16, float> fc[2][2];
#pragma unroll
    for (int i = 0; i < 2; i++)
#pragma unroll
        for (int j = 0; j < 2; j++) wmma::fill_fragment(fc[i][j], 0.f);

    int lr = tid >> 1, lp = tid & 1;
    int grow = row0 + lr;
    bool av = grow < N_NODES;
    const __half* Ap = A + (size_t)(av ? grow : 0) * K + lp * 8;

    for (int kk = 0; kk < K; kk += 16) {
        uint4 v = make_uint4(0u, 0u, 0u, 0u);
        if (av) v = *(const uint4*)(Ap + kk);
        *(uint4*)&As[lr][lp * 8] = v;
        if (tid < 128) {
            int r = tid >> 3, p = tid & 7;
            *(uint4*)&Ws[r][p * 8] =
                *(const uint4*)(W + (size_t)(kk + r) * Cn + col0 + p * 8);
        }
        __syncthreads();
        wmma::fragment<wmma::matrix_a, 16, 16, 16, __half, wmma::row_major> fa[2];
        wmma::fragment<wmma::matrix_b, 16, 16, 16, __half, wmma::row_major> fb[2];
        wmma::load_matrix_sync(fa[0], &As[wr * 32][0], 24);
        wmma::load_matrix_sync(fa[1], &As[wr * 32 + 16][0], 24);
        wmma::load_matrix_sync(fb[0], &Ws[0][wc * 32], 72);
        wmma::load_matrix_sync(fb[1], &Ws[0][wc * 32 + 16], 72);
#pragma unroll
        for (int i = 0; i < 2; i++)
#pragma unroll
            for (int j = 0; j < 2; j++)
                wmma::mma_sync(fc[i][j], fa[i], fb[j], fc[i][j]);
        __syncthreads();
    }

#pragma unroll
    for (int i = 0; i < 2; i++)
#pragma unroll
        for (int j = 0; j < 2; j++)
            wmma::store_matrix_sync(&stage[wid][(i * 16) * 32 + j * 16], fc[i][j], 32,
                                    wmma::mem_row_major);
    __syncwarp();

    int gr = row0 + wr * 32 + lane;
    if (gr < N_NODES) {
        int gc0 = col0 + wc * 32;
        const float* srow = &stage[wid][lane * 32];
        __half* orow = Out + (size_t)gr * Cn + gc0;
#pragma unroll
        for (int q = 0; q < 4; q++) {
            float4 f0 = *(const float4*)(srow + q * 8);
            float4 f1 = *(const float4*)(srow + q * 8 + 4);
            float b[8] = {0, 0, 0, 0, 0, 0, 0, 0};
            if (bias) {
                float4 bb0 = *(const float4*)(bias + gc0 + q * 8);
                float4 bb1 = *(const float4*)(bias + gc0 + q * 8 + 4);
                b[0] = bb0.x; b[1] = bb0.y; b[2] = bb0.z; b[3] = bb0.w;
                b[4] = bb1.x; b[5] = bb1.y; b[6] = bb1.z; b[7] = bb1.w;
            }
            float r[8] = {f0.x + b[0], f0.y + b[1], f0.z + b[2], f0.w + b[3],
                          f1.x + b[4], f1.y + b[5], f1.z + b[6], f1.w + b[7]};
            if (relu) {
#pragma unroll
                for (int q2 = 0; q2 < 8; q2++) r[q2] = fmaxf(r[q2], 0.f);
            }
            __half2 h0 = __floats2half2_rn(r[0], r[1]);
            __half2 h1 = __floats2half2_rn(r[2], r[3]);
            __half2 h2 = __floats2half2_rn(r[4], r[5]);
            __half2 h3 = __floats2half2_rn(r[6], r[7]);
            uint4 o;
            o.x = *(unsigned*)&h0; o.y = *(unsigned*)&h1;
            o.z = *(unsigned*)&h2; o.w = *(unsigned*)&h3;
            *(uint4*)(orow + q * 8) = o;
        }
    }
}

// ---------------- CSR aggregation: 4-deep gather MLP + double-buffered edge fetch ----------------
template <int CW, bool OUTF>
__global__ void k_agg(const __half* __restrict__ T, void* __restrict__ Optr,
                      const float* __restrict__ bias, int relu, int stride, int choff) {
    int warp = threadIdx.x >> 5;
    int lane = threadIdx.x & 31;
    int n = blockIdx.x * 8 + warp;
    float dn = g_dinv[n];
    float dn2 = dn * dn;
    int s = g_rowptr[n], e = g_rowptr[n + 1];

    if (CW == 128) {
        int o0 = choff + lane * 4;
        uint2 raw = *(const uint2*)(T + (size_t)n * stride + o0);
        float2 f0 = __half22float2(*(__half2*)&raw.x);
        float2 f1 = __half22float2(*(__half2*)&raw.y);
        float ax = f0.x * dn2, ay = f0.y * dn2, az = f1.x * dn2, aw = f1.y * dn2;

        int2 cur = make_int2(0, 0);
        if (s + lane < e) cur = g_cw[s + lane];
        for (int base = s; base < e; base += 32) {
            int nb = base + 32;
            int2 nxt = make_int2(0, 0);
            if (nb + lane < e) nxt = g_cw[nb + lane];
            int rem = e - base;
            int nt = rem < 32 ? rem : 32;
            int t = 0;
            for (; t + 4 <= nt; t += 4) {
                int u0 = __shfl_sync(0xffffffffu, cur.x, t);
                int u1 = __shfl_sync(0xffffffffu, cur.x, t + 1);
                int u2 = __shfl_sync(0xffffffffu, cur.x, t + 2);
                int u3 = __shfl_sync(0xffffffffu, cur.x, t + 3);
                float w0 = __int_as_float(__shfl_sync(0xffffffffu, cur.y, t));
                float w1 = __int_as_float(__shfl_sync(0xffffffffu, cur.y, t + 1));
                float w2 = __int_as_float(__shfl_sync(0xffffffffu, cur.y, t + 2));
                float w3 = __int_as_float(__shfl_sync(0xffffffffu, cur.y, t + 3));
                uint2 r0 = *(const uint2*)(T + (size_t)u0 * stride + o0);
                uint2 r1 = *(const uint2*)(T + (size_t)u1 * stride + o0);
                uint2 r2 = *(const uint2*)(T + (size_t)u2 * stride + o0);
                uint2 r3 = *(const uint2*)(T + (size_t)u3 * stride + o0);
                float2 p0 = __half22float2(*(__half2*)&r0.x), p1 = __half22float2(*(__half2*)&r0.y);
                float2 q0 = __half22float2(*(__half2*)&r1.x), q1 = __half22float2(*(__half2*)&r1.y);
                float2 s0 = __half22float2(*(__half2*)&r2.x), s1 = __half22float2(*(__half2*)&r2.y);
                float2 v0 = __half22float2(*(__half2*)&r3.x), v1 = __half22float2(*(__half2*)&r3.y);
                ax += w0 * p0.x + w1 * q0.x + w2 * s0.x + w3 * v0.x;
                ay += w0 * p0.y + w1 * q0.y + w2 * s0.y + w3 * v0.y;
                az += w0 * p1.x + w1 * q1.x + w2 * s1.x + w3 * v1.x;
                aw += w0 * p1.y + w1 * q1.y + w2 * s1.y + w3 * v1.y;
            }
            for (; t < nt; t++) {
                int u = __shfl_sync(0xffffffffu, cur.x, t);
                float w = __int_as_float(__shfl_sync(0xffffffffu, cur.y, t));
                uint2 r0 = *(const uint2*)(T + (size_t)u * stride + o0);
                float2 p0 = __half22float2(*(__half2*)&r0.x), p1 = __half22float2(*(__half2*)&r0.y);
                ax += w * p0.x; ay += w * p0.y; az += w * p1.x; aw += w * p1.y;
            }
            cur = nxt;
        }
        float4 b0 = make_float4(0.f, 0.f, 0.f, 0.f);
        if (bias) b0 = *(const float4*)(bias + o0);
        float rx = ax + b0.x, ry = ay + b0.y, rz = az + b0.z, rw = aw + b0.w;
        if (relu) {
            rx = fmaxf(rx, 0.f); ry = fmaxf(ry, 0.f);
            rz = fmaxf(rz, 0.f); rw = fmaxf(rw, 0.f);
        }
        if (OUTF) {
            *(float4*)((float*)Optr + (size_t)n * stride + o0) = make_float4(rx, ry, rz, rw);
        } else {
            __half2 p0 = __floats2half2_rn(rx, ry);
            __half2 p1 = __floats2half2_rn(rz, rw);
            uint2 o; o.x = *(unsigned*)&p0; o.y = *(unsigned*)&p1;
            *(uint2*)((__half*)Optr + (size_t)n * stride + o0) = o;
        }
    } else { // CW == 64
        int o0 = choff + lane * 2;
        unsigned raw = *(const unsigned*)(T + (size_t)n * stride + o0);
        float2 f0 = __half22float2(*(__half2*)&raw);
        float ax = f0.x * dn2, ay = f0.y * dn2;
        int2 cur = make_int2(0, 0);
        if (s + lane < e) cur = g_cw[s + lane];
        for (int base = s; base < e; base += 32) {
            int nb = base + 32;
            int2 nxt = make_int2(0, 0);
            if (nb + lane < e) nxt = g_cw[nb + lane];
            int rem = e - base;
            int nt = rem < 32 ? rem : 32;
            int t = 0;
            for (; t + 4 <= nt; t += 4) {
                int u0 = __shfl_sync(0xffffffffu, cur.x, t);
                int u1 = __shfl_sync(0xffffffffu, cur.x, t + 1);
                int u2 = __shfl_sync(0xffffffffu, cur.x, t + 2);
                int u3 = __shfl_sync(0xffffffffu, cur.x, t + 3);
                float w0 = __int_as_float(__shfl_sync(0xffffffffu, cur.y, t));
                float w1 = __int_as_float(__shfl_sync(0xffffffffu, cur.y, t + 1));
                float w2 = __int_as_float(__shfl_sync(0xffffffffu, cur.y, t + 2));
                float w3 = __int_as_float(__shfl_sync(0xffffffffu, cur.y, t + 3));
                unsigned r0 = *(const unsigned*)(T + (size_t)u0 * stride + o0);
                unsigned r1 = *(const unsigned*)(T + (size_t)u1 * stride + o0);
                unsigned r2 = *(const unsigned*)(T + (size_t)u2 * stride + o0);
                unsigned r3 = *(const unsigned*)(T + (size_t)u3 * stride + o0);
                float2 p0 = __half22float2(*(__half2*)&r0);
                float2 p1 = __half22float2(*(__half2*)&r1);
                float2 p2 = __half22float2(*(__half2*)&r2);
                float2 p3 = __half22float2(*(__half2*)&r3);
                ax += w0 * p0.x + w1 * p1.x + w2 * p2.x + w3 * p3.x;
                ay += w0 * p0.y + w1 * p1.y + w2 * p2.y + w3 * p3.y;
            }
            for (; t < nt; t++) {
                int u = __shfl_sync(0xffffffffu, cur.x, t);
                float w = __int_as_float(__shfl_sync(0xffffffffu, cur.y, t));
                unsigned r0 = *(const unsigned*)(T + (size_t)u * stride + o0);
                float2 p0 = __half22float2(*(__half2*)&r0);
                ax += w * p0.x; ay += w * p0.y;
            }
            cur = nxt;
        }
        float2 b0 = make_float2(0.f, 0.f);
        if (bias) b0 = *(const float2*)(bias + o0);
        float rx = ax + b0.x, ry = ay + b0.y;
        if (relu) { rx = fmaxf(rx, 0.f); ry = fmaxf(ry, 0.f); }
        if (OUTF) {
            *(float2*)((float*)Optr + (size_t)n * stride + o0) = make_float2(rx, ry);
        } else {
            __half2 p0 = __floats2half2_rn(rx, ry);
            *(unsigned*)((__half*)Optr + (size_t)n * stride + o0) = *(unsigned*)&p0;
        }
    }
}

// ---------------- pooling: run-length accumulate over 8 consecutive nodes ----------------
__global__ void k_pool(const float* __restrict__ h, const int* __restrict__ batch) {
    int idx = blockIdx.x * blockDim.x + threadIdx.x;
    if (idx >= (N_NODES / 8) * 16) return;
    int grp = idx >> 4, q = idx & 15;
    int n0 = grp * 8;
    float4 acc = make_float4(0.f, 0.f, 0.f, 0.f);
    int curg = batch[n0];
#pragma unroll
    for (int i = 0; i < 8; i++) {
        int n = n0 + i;
        int g = batch[n];
        float4 v = *(const float4*)(h + (size_t)n * 64 + q * 4);
        if (g != curg) {
            float* p = g_pool + curg * 64 + q * 4;
            atomicAdd(p + 0, acc.x); atomicAdd(p + 1, acc.y);
            atomicAdd(p + 2, acc.z); atomicAdd(p + 3, acc.w);
            acc = make_float4(0.f, 0.f, 0.f, 0.f);
            curg = g;
        }
        acc.x += v.x; acc.y += v.y; acc.z += v.z; acc.w += v.w;
    }
    float* p = g_pool + curg * 64 + q * 4;
    atomicAdd(p + 0, acc.x); atomicAdd(p + 1, acc.y);
    atomicAdd(p + 2, acc.z); atomicAdd(p + 3, acc.w);
}

// ---------------- counts via binary search over sorted batch ----------------
__global__ void k_cnt(const int* __restrict__ batch) {
    int g = blockIdx.x * blockDim.x + threadIdx.x;
    if (g >= N_GRAPHS) return;
    int lo = 0, hi = N_NODES;
    while (lo < hi) { int m = (lo + hi) >> 1; if (batch[m] < g) lo = m + 1; else hi = m; }
    int a = lo;
    lo = a; hi = N_NODES;
    while (lo < hi) { int m = (lo + hi) >> 1; if (batch[m] < g + 1) lo = m + 1; else hi = m; }
    g_cnt[g] = lo - a;
}

// ---------------- head ----------------
__global__ void k_final(const float* __restrict__ Wlin, const float* __restrict__ blin,
                        float* __restrict__ out) {
    int g = blockIdx.x;
    int t = threadIdx.x;  // 64 threads
    __shared__ float mean[64];
    __shared__ float logits[10];
    __shared__ float red2[2];
    float c = (float)g_cnt[g];
    float inv = 1.0f / fmaxf(c, 1.0f);
    mean[t] = g_pool[g * 64 + t] * inv;
    __syncthreads();
    if (t < 10) {
        float s = blin[t];
        for (int k = 0; k < 64; k++) s += mean[k] * Wlin[k * 10 + t];
        logits[t] = s;
    }
    __syncthreads();
    if (t == 0) {
        float mx = logits[0];
        for (int l = 1; l < 10; l++) mx = fmaxf(mx, logits[l]);
        float se = 0.f;
        for (int l = 0; l < 10; l++) se += expf(logits[l] - mx);
        red2[0] = mx;
        red2[1] = se;
    }
    __syncthreads();
    if (t < 10) {
        float lsm = logits[t] - red2[0] - logf(red2[1]);
        out[g * 10 + t] = lsm;
        out[N_GRAPHS * 10 + g * 10 + t] = expf(lsm);
    }
}

// ---------------- launch ----------------
extern "C" void kernel_launch(void* const* d_in, const int* in_sizes, int n_in,
                              void* d_out, int out_size) {
    const float* x     = (const float*)d_in[0];
    const int*   ei    = (const int*)d_in[1];
    const int*   batch = (const int*)d_in[2];
    const float* W1 = (const float*)d_in[4];  const float* b1 = (const float*)d_in[5];
    const float* W2 = (const float*)d_in[6];  const float* b2 = (const float*)d_in[7];
    const float* W3 = (const float*)d_in[8];  const float* b3 = (const float*)d_in[9];
    const float* W4 = (const float*)d_in[10]; const float* b4 = (const float*)d_in[11];
    const float* W5 = (const float*)d_in[12]; const float* b5 = (const float*)d_in[13];
    const float* W6 = (const float*)d_in[14]; const float* b6 = (const float*)d_in[15];
    const float* Wlin = (const float*)d_in[16];
    const float* blin = (const float*)d_in[17];
    const int* src = ei;
    const int* dst = ei + N_EDGES;
    float* out = (float*)d_out;

    __half *hA, *hB, *Wh;
    float *h6;
    cudaGetSymbolAddress((void**)&hA, g_hA);
    cudaGetSymbolAddress((void**)&hB, g_hB);
    cudaGetSymbolAddress((void**)&h6, g_h6);
    cudaGetSymbolAddress((void**)&Wh, g_Wh);

    const int TB = 256;
    int gN = (N_NODES + TB - 1) / TB;
    int gE = (N_EDGES + TB - 1) / TB;

    // preprocessing (+ converts)
    k_init<<<gN, TB>>>();
    k_tohalf<<<(N_NODES * 32 + TB - 1) / TB, TB>>>(x);
    k_wconv_all<<<(110592 + TB - 1) / TB, TB>>>(W1, W2, W3, W4, W5, W6);
    k_hist<<<gE, TB>>>(dst);
    k_scan1<<<NBLK, 1024>>>();
    k_scan2<<<1, 128>>>();
    k_scan3<<<NBLK, 1024>>>();
    k_fill<<<gE, TB>>>(src, dst);
    k_cnt<<<2, 256>>>(batch);

    int aggBlocks = N_NODES / 8;
    dim3 g256(4, 782), g128(2, 782), g64(1, 782);

    // L1: aggregate-first (128 ch) on half x, then GEMM 128->256 (+bias+relu)
    k_agg<128, false><<<aggBlocks, 256>>>(hA, hB, nullptr, 0, 128, 0);
    k_gemm<<<g256, 256>>>(hB, Wh + OFF_W1, hA, 128, 256, b1, 1);
    // L2: transform-first, split agg
    k_gemm<<<g256, 256>>>(hA, Wh + OFF_W2, hB, 256, 256, nullptr, 0);
    k_agg<128, false><<<aggBlocks, 256>>>(hB, hA, b2, 1, 256, 0);
    k_agg<128, false><<<aggBlocks, 256>>>(hB, hA, b2, 1, 256, 128);
    // L3
    k_gemm<<<g256, 256>>>(hA, Wh + OFF_W3, hB, 256, 256, nullptr, 0);
    k_agg<128, false><<<aggBlocks, 256>>>(hB, hA, b3, 1, 256, 0);
    k_agg<128, false><<<aggBlocks, 256>>>(hB, hA, b3, 1, 256, 128);
    // L4: 256->128
    k_gemm<<<g128, 256>>>(hA, Wh + OFF_W4, hB, 256, 128, nullptr, 0);
    k_agg<128, false><<<aggBlocks, 256>>>(hB, hA, b4, 1, 128, 0);
    // L5: 128->128
    k_gemm<<<g128, 256>>>(hA, Wh + OFF_W5, hB, 128, 128, nullptr, 0);
    k_agg<128, false><<<aggBlocks, 256>>>(hB, hA, b5, 1, 128, 0);
    // L6: 128->64, no relu; agg writes fp32 for pooling
    k_gemm<<<g64, 256>>>(hA, Wh + OFF_W6, hB, 128, 64, nullptr, 0);
    k_agg<64, true><<<aggBlocks, 256>>>(hB, h6, b6, 0, 64, 0);

    // pooling + head
    k_pool<<<((N_NODES / 8) * 16 + TB - 1) / TB, TB>>>(h6, batch);
    k_final<<<N_GRAPHS, 64>>>(Wlin, blin, out);
}

// round 14
// speedup vs baseline: 1.1264x; 1.0432x over previous
#include <cuda_runtime.h>
#include <cuda_fp16.h>
#include <mma.h>
#include <math.h>

using namespace nvcuda;

#define N_NODES  100000
#define N_EDGES  3200000
#define N_GRAPHS 512
#define NBLK     98          // ceil(100000/1024)

// ---------------- scratch (static device globals; no allocation) ----------------
__device__ __half g_hA[(size_t)N_NODES * 256];
__device__ __half g_hB[(size_t)N_NODES * 256];
__device__ float  g_h6[(size_t)N_NODES * 64];   // final layer output (fp32 for pooling)
__device__ __half g_Wh[262144];                 // all W matrices in half (offsets below)
__device__ int    g_deg[N_NODES];
__device__ float  g_dinv[N_NODES];
__device__ int    g_rowptr[N_NODES + 1];
__device__ int    g_cursor[N_NODES];
__device__ int2   g_cw[N_EDGES];                // packed (src, weight)
__device__ int    g_bsum[128];
__device__ float  g_pool[N_GRAPHS * 64];
__device__ int    g_cnt[N_GRAPHS];

// W offsets in g_Wh (half elements)
#define OFF_W1 0           // 128*256 = 32768
#define OFF_W2 32768       // 256*256 = 65536
#define OFF_W3 98304       // 65536
#define OFF_W4 163840      // 256*128 = 32768
#define OFF_W5 196608      // 128*128 = 16384
#define OFF_W6 212992      // 128*64  = 8192

// ---------------- init ----------------
__global__ void k_init() {
    int i = blockIdx.x * blockDim.x + threadIdx.x;
    if (i < N_NODES) g_deg[i] = 1;               // self loop
    if (i < N_GRAPHS * 64) g_pool[i] = 0.f;
}

// ---------------- fp32 -> half converts ----------------
__global__ void k_tohalf(const float* __restrict__ x) {
    int i = blockIdx.x * blockDim.x + threadIdx.x;   // one float4 -> 4 halves
    if (i >= N_NODES * 32) return;
    float4 v = *(const float4*)(x + (size_t)i * 4);
    __half2 h0 = __floats2half2_rn(v.x, v.y);
    __half2 h1 = __floats2half2_rn(v.z, v.w);
    uint2 o; o.x = *(unsigned*)&h0; o.y = *(unsigned*)&h1;
    *(uint2*)(g_hA + (size_t)i * 4) = o;
}

// all six W matrices in one kernel; i indexes half2 pairs (110592 total)
__global__ void k_wconv_all(const float* __restrict__ W1, const float* __restrict__ W2,
                            const float* __restrict__ W3, const float* __restrict__ W4,
                            const float* __restrict__ W5, const float* __restrict__ W6) {
    int i = blockIdx.x * blockDim.x + threadIdx.x;
    if (i >= 110592) return;
    const float* src;
    int off, loc;
    if (i < 16384)       { src = W1; off = OFF_W1; loc = i; }
    else if (i < 49152)  { src = W2; off = OFF_W2; loc = i - 16384; }
    else if (i < 81920)  { src = W3; off = OFF_W3; loc = i - 49152; }
    else if (i < 98304)  { src = W4; off = OFF_W4; loc = i - 81920; }
    else if (i < 106496) { src = W5; off = OFF_W5; loc = i - 98304; }
    else                 { src = W6; off = OFF_W6; loc = i - 106496; }
    float2 v = *(const float2*)(src + loc * 2);
    __half2 h = __floats2half2_rn(v.x, v.y);
    *(unsigned*)(g_Wh + off + loc * 2) = *(unsigned*)&h;
}

// ---------------- degree histogram over dst ----------------
__global__ void k_hist(const int* __restrict__ dst) {
    int i = blockIdx.x * blockDim.x + threadIdx.x;
    if (i < N_EDGES) atomicAdd(&g_deg[dst[i]], 1);
}

// ---------------- 3-phase multi-block exclusive scan of (deg-1) ----------------
__global__ void k_scan1() {
    __shared__ int ws[32];
    int t = threadIdx.x;
    int i = blockIdx.x * 1024 + t;
    int v = (i < N_NODES) ? (g_deg[i] - 1) : 0;
    int lane = t & 31, wid = t >> 5;
    int x = v;
#pragma unroll
    for (int off = 1; off < 32; off <<= 1) {
        int y = __shfl_up_sync(0xffffffffu, x, off);
        if (lane >= off) x += y;
    }
    if (lane == 31) ws[wid] = x;
    __syncthreads();
    if (wid == 0) {
        int s = ws[lane];
#pragma unroll
        for (int off = 1; off < 32; off <<= 1) {
            int y = __shfl_up_sync(0xffffffffu, s, off);
            if (lane >= off) s += y;
        }
        ws[lane] = s;
    }
    __syncthreads();
    int excl = (wid ? ws[wid - 1] : 0) + (x - v);
    if (i < N_NODES) g_rowptr[i] = excl;
    if (t == 0) g_bsum[blockIdx.x] = ws[31];
}

__global__ void k_scan2() {
    __shared__ int ws[4];
    int t = threadIdx.x;
    int v = (t < NBLK) ? g_bsum[t] : 0;
    int lane = t & 31, wid = t >> 5;
    int x = v;
#pragma unroll
    for (int off = 1; off < 32; off <<= 1) {
        int y = __shfl_up_sync(0xffffffffu, x, off);
        if (lane >= off) x += y;
    }
    if (lane == 31) ws[wid] = x;
    __syncthreads();
    int add = 0;
    for (int w = 0; w < wid; w++) add += ws[w];
    if (t < NBLK) g_bsum[t] = add + x - v;
}

__global__ void k_scan3() {
    int i = blockIdx.x * 1024 + threadIdx.x;
    if (i < N_NODES) {
        int v = g_rowptr[i] + g_bsum[blockIdx.x];
        g_rowptr[i] = v;
        g_cursor[i] = v;
        g_dinv[i] = rsqrtf((float)g_deg[i]);
    }
    if (i == 0) g_rowptr[N_NODES] = N_EDGES;
}

// fill CSR with packed (src, dinv[src]*dinv[dst])
__global__ void k_fill(const int* __restrict__ src, const int* __restrict__ dst) {
    int i = blockIdx.x * blockDim.x + threadIdx.x;
    if (i < N_EDGES) {
        int d = dst[i];
        int s = src[i];
        float w = g_dinv[s] * g_dinv[d];
        int p = atomicAdd(&g_cursor[d], 1);
        g_cw[p] = make_int2(s, __float_as_int(w));
    }
}

// ---------------- wmma GEMM: Out[N,Cn](half) = A[N,K](half) @ Wh[K,Cn](half) + bias, relu ----------------
__global__ __launch_bounds__(256) void k_gemm(const __half* __restrict__ A,
                                              const __half* __restrict__ W,
                                              __half* __restrict__ Out,
                                              int K, int Cn,
                                              const float* __restrict__ bias, int relu) {
    __shared__ __half As[128][24];
    __shared__ __half Ws[16][72];
    __shared__ float  stage[8][1024];

    int tid = threadIdx.x;
    int wid = tid >> 5, lane = tid & 31;
    int wr = wid & 3, wc = wid >> 2;
    int row0 = blockIdx.y * 128, col0 = blockIdx.x * 64;

    wmma::fragment<wmma::accumulator, 16, 16, 16, float> fc[2][2];
#pragma unroll
    for (int i = 0; i < 2; i++)
#pragma unroll
        for (int j = 0; j < 2; j++) wmma::fill_fragment(fc[i][j], 0.f);

    int lr = tid >> 1, lp = tid & 1;
    int grow = row0 + lr;
    bool av = grow < N_NODES;
    const __half* Ap = A + (size_t)(av ? grow : 0) * K + lp * 8;

    for (int kk = 0; kk < K; kk += 16) {
        uint4 v = make_uint4(0u, 0u, 0u, 0u);
        if (av) v = *(const uint4*)(Ap + kk);
        *(uint4*)&As[lr][lp * 8] = v;
        if (tid < 128) {
            int r = tid >> 3, p = tid & 7;
            *(uint4*)&Ws[r][p * 8] =
                *(const uint4*)(W + (size_t)(kk + r) * Cn + col0 + p * 8);
        }
        __syncthreads();
        wmma::fragment<wmma::matrix_a, 16, 16, 16, __half, wmma::row_major> fa[2];
        wmma::fragment<wmma::matrix_b, 16, 16, 16, __half, wmma::row_major> fb[2];
        wmma::load_matrix_sync(fa[0], &As[wr * 32][0], 24);
        wmma::load_matrix_sync(fa[1], &As[wr * 32 + 16][0], 24);
        wmma::load_matrix_sync(fb[0], &Ws[0][wc * 32], 72);
        wmma::load_matrix_sync(fb[1], &Ws[0][wc * 32 + 16], 72);
#pragma unroll
        for (int i = 0; i < 2; i++)
#pragma unroll
            for (int j = 0; j < 2; j++)
                wmma::mma_sync(fc[i][j], fa[i], fb[j], fc[i][j]);
        __syncthreads();
    }

#pragma unroll
    for (int i = 0; i < 2; i++)
#pragma unroll
        for (int j = 0; j < 2; j++)
            wmma::store_matrix_sync(&stage[wid][(i * 16) * 32 + j * 16], fc[i][j], 32,
                                    wmma::mem_row_major);
    __syncwarp();

    int gr = row0 + wr * 32 + lane;
    if (gr < N_NODES) {
        int gc0 = col0 + wc * 32;
        const float* srow = &stage[wid][lane * 32];
        __half* orow = Out + (size_t)gr * Cn + gc0;
#pragma unroll
        for (int q = 0; q < 4; q++) {
            float4 f0 = *(const float4*)(srow + q * 8);
            float4 f1 = *(const float4*)(srow + q * 8 + 4);
            float b[8] = {0, 0, 0, 0, 0, 0, 0, 0};
            if (bias) {
                float4 bb0 = *(const float4*)(bias + gc0 + q * 8);
                float4 bb1 = *(const float4*)(bias + gc0 + q * 8 + 4);
                b[0] = bb0.x; b[1] = bb0.y; b[2] = bb0.z; b[3] = bb0.w;
                b[4] = bb1.x; b[5] = bb1.y; b[6] = bb1.z; b[7] = bb1.w;
            }
            float r[8] = {f0.x + b[0], f0.y + b[1], f0.z + b[2], f0.w + b[3],
                          f1.x + b[4], f1.y + b[5], f1.z + b[6], f1.w + b[7]};
            if (relu) {
#pragma unroll
                for (int q2 = 0; q2 < 8; q2++) r[q2] = fmaxf(r[q2], 0.f);
            }
            __half2 h0 = __floats2half2_rn(r[0], r[1]);
            __half2 h1 = __floats2half2_rn(r[2], r[3]);
            __half2 h2 = __floats2half2_rn(r[4], r[5]);
            __half2 h3 = __floats2half2_rn(r[6], r[7]);
            uint4 o;
            o.x = *(unsigned*)&h0; o.y = *(unsigned*)&h1;
            o.z = *(unsigned*)&h2; o.w = *(unsigned*)&h3;
            *(uint4*)(orow + q * 8) = o;
        }
    }
}

// ---------------- CSR aggregation: exact R6 inner loop (4-deep MLP, in-loop edge fetch) ----------------
// channel half selected by blockIdx.y (choff = blockIdx.y * 128)
template <int CW, bool OUTF>
__global__ void k_agg(const __half* __restrict__ T, void* __restrict__ Optr,
                      const float* __restrict__ bias, int relu, int stride) {
    int warp = threadIdx.x >> 5;
    int lane = threadIdx.x & 31;
    int n = blockIdx.x * 8 + warp;
    int choff = blockIdx.y * 128;
    float dn = g_dinv[n];
    float dn2 = dn * dn;
    int s = g_rowptr[n], e = g_rowptr[n + 1];

    if (CW == 128) {
        int o0 = choff + lane * 4;
        uint2 raw = *(const uint2*)(T + (size_t)n * stride + o0);
        float2 f0 = __half22float2(*(__half2*)&raw.x);
        float2 f1 = __half22float2(*(__half2*)&raw.y);
        float ax = f0.x * dn2, ay = f0.y * dn2, az = f1.x * dn2, aw = f1.y * dn2;

        for (int base = s; base < e; base += 32) {
            int rem = e - base;
            int2 cw = make_int2(0, 0);
            if (lane < rem) cw = g_cw[base + lane];
            int nt = rem < 32 ? rem : 32;
            int t = 0;
            for (; t + 4 <= nt; t += 4) {
                int u0 = __shfl_sync(0xffffffffu, cw.x, t);
                int u1 = __shfl_sync(0xffffffffu, cw.x, t + 1);
                int u2 = __shfl_sync(0xffffffffu, cw.x, t + 2);
                int u3 = __shfl_sync(0xffffffffu, cw.x, t + 3);
                float w0 = __int_as_float(__shfl_sync(0xffffffffu, cw.y, t));
                float w1 = __int_as_float(__shfl_sync(0xffffffffu, cw.y, t + 1));
                float w2 = __int_as_float(__shfl_sync(0xffffffffu, cw.y, t + 2));
                float w3 = __int_as_float(__shfl_sync(0xffffffffu, cw.y, t + 3));
                uint2 r0 = *(const uint2*)(T + (size_t)u0 * stride + o0);
                uint2 r1 = *(const uint2*)(T + (size_t)u1 * stride + o0);
                uint2 r2 = *(const uint2*)(T + (size_t)u2 * stride + o0);
                uint2 r3 = *(const uint2*)(T + (size_t)u3 * stride + o0);
                float2 p0 = __half22float2(*(__half2*)&r0.x), p1 = __half22float2(*(__half2*)&r0.y);
                float2 q0 = __half22float2(*(__half2*)&r1.x), q1 = __half22float2(*(__half2*)&r1.y);
                float2 s0 = __half22float2(*(__half2*)&r2.x), s1 = __half22float2(*(__half2*)&r2.y);
                float2 v0 = __half22float2(*(__half2*)&r3.x), v1 = __half22float2(*(__half2*)&r3.y);
                ax += w0 * p0.x + w1 * q0.x + w2 * s0.x + w3 * v0.x;
                ay += w0 * p0.y + w1 * q0.y + w2 * s0.y + w3 * v0.y;
                az += w0 * p1.x + w1 * q1.x + w2 * s1.x + w3 * v1.x;
                aw += w0 * p1.y + w1 * q1.y + w2 * s1.y + w3 * v1.y;
            }
            for (; t < nt; t++) {
                int u = __shfl_sync(0xffffffffu, cw.x, t);
                float w = __int_as_float(__shfl_sync(0xffffffffu, cw.y, t));
                uint2 r0 = *(const uint2*)(T + (size_t)u * stride + o0);
                float2 p0 = __half22float2(*(__half2*)&r0.x), p1 = __half22float2(*(__half2*)&r0.y);
                ax += w * p0.x; ay += w * p0.y; az += w * p1.x; aw += w * p1.y;
            }
        }
        float4 b0 = make_float4(0.f, 0.f, 0.f, 0.f);
        if (bias) b0 = *(const float4*)(bias + o0);
        float rx = ax + b0.x, ry = ay + b0.y, rz = az + b0.z, rw = aw + b0.w;
        if (relu) {
            rx = fmaxf(rx, 0.f); ry = fmaxf(ry, 0.f);
            rz = fmaxf(rz, 0.f); rw = fmaxf(rw, 0.f);
        }
        if (OUTF) {
            *(float4*)((float*)Optr + (size_t)n * stride + o0) = make_float4(rx, ry, rz, rw);
        } else {
            __half2 p0 = __floats2half2_rn(rx, ry);
            __half2 p1 = __floats2half2_rn(rz, rw);
            uint2 o; o.x = *(unsigned*)&p0; o.y = *(unsigned*)&p1;
            *(uint2*)((__half*)Optr + (size_t)n * stride + o0) = o;
        }
    } else { // CW == 64
        int o0 = choff + lane * 2;
        unsigned raw = *(const unsigned*)(T + (size_t)n * stride + o0);
        float2 f0 = __half22float2(*(__half2*)&raw);
        float ax = f0.x * dn2, ay = f0.y * dn2;
        for (int base = s; base < e; base += 32) {
            int rem = e - base;
            int2 cw = make_int2(0, 0);
            if (lane < rem) cw = g_cw[base + lane];
            int nt = rem < 32 ? rem : 32;
            int t = 0;
            for (; t + 4 <= nt; t += 4) {
                int u0 = __shfl_sync(0xffffffffu, cw.x, t);
                int u1 = __shfl_sync(0xffffffffu, cw.x, t + 1);
                int u2 = __shfl_sync(0xffffffffu, cw.x, t + 2);
                int u3 = __shfl_sync(0xffffffffu, cw.x, t + 3);
                float w0 = __int_as_float(__shfl_sync(0xffffffffu, cw.y, t));
                float w1 = __int_as_float(__shfl_sync(0xffffffffu, cw.y, t + 1));
                float w2 = __int_as_float(__shfl_sync(0xffffffffu, cw.y, t + 2));
                float w3 = __int_as_float(__shfl_sync(0xffffffffu, cw.y, t + 3));
                unsigned r0 = *(const unsigned*)(T + (size_t)u0 * stride + o0);
                unsigned r1 = *(const unsigned*)(T + (size_t)u1 * stride + o0);
                unsigned r2 = *(const unsigned*)(T + (size_t)u2 * stride + o0);
                unsigned r3 = *(const unsigned*)(T + (size_t)u3 * stride + o0);
                float2 p0 = __half22float2(*(__half2*)&r0);
                float2 p1 = __half22float2(*(__half2*)&r1);
                float2 p2 = __half22float2(*(__half2*)&r2);
                float2 p3 = __half22float2(*(__half2*)&r3);
                ax += w0 * p0.x + w1 * p1.x + w2 * p2.x + w3 * p3.x;
                ay += w0 * p0.y + w1 * p1.y + w2 * p2.y + w3 * p3.y;
            }
            for (; t < nt; t++) {
                int u = __shfl_sync(0xffffffffu, cw.x, t);
                float w = __int_as_float(__shfl_sync(0xffffffffu, cw.y, t));
                unsigned r0 = *(const unsigned*)(T + (size_t)u * stride + o0);
                float2 p0 = __half22float2(*(__half2*)&r0);
                ax += w * p0.x; ay += w * p0.y;
            }
        }
        float2 b0 = make_float2(0.f, 0.f);
        if (bias) b0 = *(const float2*)(bias + o0);
        float rx = ax + b0.x, ry = ay + b0.y;
        if (relu) { rx = fmaxf(rx, 0.f); ry = fmaxf(ry, 0.f); }
        if (OUTF) {
            *(float2*)((float*)Optr + (size_t)n * stride + o0) = make_float2(rx, ry);
        } else {
            __half2 p0 = __floats2half2_rn(rx, ry);
            *(unsigned*)((__half*)Optr + (size_t)n * stride + o0) = *(unsigned*)&p0;
        }
    }
}

// ---------------- pooling: run-length accumulate over 8 consecutive nodes ----------------
__global__ void k_pool(const float* __restrict__ h, const int* __restrict__ batch) {
    int idx = blockIdx.x * blockDim.x + threadIdx.x;
    if (idx >= (N_NODES / 8) * 16) return;
    int grp = idx >> 4, q = idx & 15;
    int n0 = grp * 8;
    float4 acc = make_float4(0.f, 0.f, 0.f, 0.f);
    int curg = batch[n0];
#pragma unroll
    for (int i = 0; i < 8; i++) {
        int n = n0 + i;
        int g = batch[n];
        float4 v = *(const float4*)(h + (size_t)n * 64 + q * 4);
        if (g != curg) {
            float* p = g_pool + curg * 64 + q * 4;
            atomicAdd(p + 0, acc.x); atomicAdd(p + 1, acc.y);
            atomicAdd(p + 2, acc.z); atomicAdd(p + 3, acc.w);
            acc = make_float4(0.f, 0.f, 0.f, 0.f);
            curg = g;
        }
        acc.x += v.x; acc.y += v.y; acc.z += v.z; acc.w += v.w;
    }
    float* p = g_pool + curg * 64 + q * 4;
    atomicAdd(p + 0, acc.x); atomicAdd(p + 1, acc.y);
    atomicAdd(p + 2, acc.z); atomicAdd(p + 3, acc.w);
}

// ---------------- counts via binary search over sorted batch ----------------
__global__ void k_cnt(const int* __restrict__ batch) {
    int g = blockIdx.x * blockDim.x + threadIdx.x;
    if (g >= N_GRAPHS) return;
    int lo = 0, hi = N_NODES;
    while (lo < hi) { int m = (lo + hi) >> 1; if (batch[m] < g) lo = m + 1; else hi = m; }
    int a = lo;
    lo = a; hi = N_NODES;
    while (lo < hi) { int m = (lo + hi) >> 1; if (batch[m] < g + 1) lo = m + 1; else hi = m; }
    g_cnt[g] = lo - a;
}

// ---------------- head ----------------
__global__ void k_final(const float* __restrict__ Wlin, const float* __restrict__ blin,
                        float* __restrict__ out) {
    int g = blockIdx.x;
    int t = threadIdx.x;  // 64 threads
    __shared__ float mean[64];
    __shared__ float logits[10];
    __shared__ float red2[2];
    float c = (float)g_cnt[g];
    float inv = 1.0f / fmaxf(c, 1.0f);
    mean[t] = g_pool[g * 64 + t] * inv;
    __syncthreads();
    if (t < 10) {
        float s = blin[t];
        for (int k = 0; k < 64; k++) s += mean[k] * Wlin[k * 10 + t];
        logits[t] = s;
    }
    __syncthreads();
    if (t == 0) {
        float mx = logits[0];
        for (int l = 1; l < 10; l++) mx = fmaxf(mx, logits[l]);
        float se = 0.f;
        for (int l = 0; l < 10; l++) se += expf(logits[l] - mx);
        red2[0] = mx;
        red2[1] = se;
    }
    __syncthreads();
    if (t < 10) {
        float lsm = logits[t] - red2[0] - logf(red2[1]);
        out[g * 10 + t] = lsm;
        out[N_GRAPHS * 10 + g * 10 + t] = expf(lsm);
    }
}

// ---------------- launch ----------------
extern "C" void kernel_launch(void* const* d_in, const int* in_sizes, int n_in,
                              void* d_out, int out_size) {
    const float* x     = (const float*)d_in[0];
    const int*   ei    = (const int*)d_in[1];
    const int*   batch = (const int*)d_in[2];
    const float* W1 = (const float*)d_in[4];  const float* b1 = (const float*)d_in[5];
    const float* W2 = (const float*)d_in[6];  const float* b2 = (const float*)d_in[7];
    const float* W3 = (const float*)d_in[8];  const float* b3 = (const float*)d_in[9];
    const float* W4 = (const float*)d_in[10]; const float* b4 = (const float*)d_in[11];
    const float* W5 = (const float*)d_in[12]; const float* b5 = (const float*)d_in[13];
    const float* W6 = (const float*)d_in[14]; const float* b6 = (const float*)d_in[15];
    const float* Wlin = (const float*)d_in[16];
    const float* blin = (const float*)d_in[17];
    const int* src = ei;
    const int* dst = ei + N_EDGES;
    float* out = (float*)d_out;

    __half *hA, *hB, *Wh;
    float *h6;
    cudaGetSymbolAddress((void**)&hA, g_hA);
    cudaGetSymbolAddress((void**)&hB, g_hB);
    cudaGetSymbolAddress((void**)&h6, g_h6);
    cudaGetSymbolAddress((void**)&Wh, g_Wh);

    const int TB = 256;
    int gN = (N_NODES + TB - 1) / TB;
    int gE = (N_EDGES + TB - 1) / TB;

    // preprocessing (+ converts)
    k_init<<<gN, TB>>>();
    k_tohalf<<<(N_NODES * 32 + TB - 1) / TB, TB>>>(x);
    k_wconv_all<<<(110592 + TB - 1) / TB, TB>>>(W1, W2, W3, W4, W5, W6);
    k_hist<<<gE, TB>>>(dst);
    k_scan1<<<NBLK, 1024>>>();
    k_scan2<<<1, 128>>>();
    k_scan3<<<NBLK, 1024>>>();
    k_fill<<<gE, TB>>>(src, dst);
    k_cnt<<<2, 256>>>(batch);

    int aggBlocks = N_NODES / 8;
    dim3 agg1(aggBlocks, 1), agg2(aggBlocks, 2);
    dim3 g256(4, 782), g128(2, 782), g64(1, 782);

    // L1: aggregate-first (128 ch) on half x, then GEMM 128->256 (+bias+relu)
    k_agg<128, false><<<agg1, 256>>>(hA, hB, nullptr, 0, 128);
    k_gemm<<<g256, 256>>>(hB, Wh + OFF_W1, hA, 128, 256, b1, 1);
    // L2: transform-first, both channel halves in one launch (gridDim.y=2)
    k_gemm<<<g256, 256>>>(hA, Wh + OFF_W2, hB, 256, 256, nullptr, 0);
    k_agg<128, false><<<agg2, 256>>>(hB, hA, b2, 1, 256);
    // L3
    k_gemm<<<g256, 256>>>(hA, Wh + OFF_W3, hB, 256, 256, nullptr, 0);
    k_agg<128, false><<<agg2, 256>>>(hB, hA, b3, 1, 256);
    // L4: 256->128
    k_gemm<<<g128, 256>>>(hA, Wh + OFF_W4, hB, 256, 128, nullptr, 0);
    k_agg<128, false><<<agg1, 256>>>(hB, hA, b4, 1, 128);
    // L5: 128->128
    k_gemm<<<g128, 256>>>(hA, Wh + OFF_W5, hB, 128, 128, nullptr, 0);
    k_agg<128, false><<<agg1, 256>>>(hB, hA, b5, 1, 128);
    // L6: 128->64, no relu; agg writes fp32 for pooling
    k_gemm<<<g64, 256>>>(hA, Wh + OFF_W6, hB, 128, 64, nullptr, 0);
    k_agg<64, true><<<agg1, 256>>>(hB, h6, b6, 0, 64);

    // pooling + head
    k_pool<<<((N_NODES / 8) * 16 + TB - 1) / TB, TB>>>(h6, batch);
    k_final<<<N_GRAPHS, 64>>>(Wlin, blin, out);
}

// round 15
// speedup vs baseline: 1.1431x; 1.0148x over previous
#include <cuda_runtime.h>
#include <cuda_fp16.h>
#include <mma.h>
#include <math.h>

using namespace nvcuda;

#define N_NODES  100000
#define N_EDGES  3200000
#define N_GRAPHS 512
#define NBLK     98          // ceil(100000/1024)

// ---------------- scratch (static device globals; no allocation) ----------------
__device__ __half g_hA[(size_t)N_NODES * 256];
__device__ __half g_hB[(size_t)N_NODES * 256];
__device__ unsigned char g_q8[(size_t)N_NODES * 256];  // fp8 e4m3 activations (L2/L3)
__device__ float  g_h6[(size_t)N_NODES * 64];   // final layer output (fp32 for pooling)
__device__ __half g_Wh[262144];                 // all W matrices in half (offsets below)
__device__ int    g_deg[N_NODES];
__device__ float  g_dinv[N_NODES];
__device__ int    g_rowptr[N_NODES + 1];
__device__ int    g_cursor[N_NODES];
__device__ int2   g_cw[N_EDGES];                // packed (src, weight)
__device__ int    g_bsum[128];
__device__ float  g_pool[N_GRAPHS * 64];
__device__ int    g_cnt[N_GRAPHS];

// W offsets in g_Wh (half elements)
#define OFF_W1 0           // 128*256 = 32768
#define OFF_W2 32768       // 256*256 = 65536
#define OFF_W3 98304       // 65536
#define OFF_W4 163840      // 256*128 = 32768
#define OFF_W5 196608      // 128*128 = 16384
#define OFF_W6 212992      // 128*64  = 8192

// ---------------- fp8 helpers ----------------
// pack two f32 -> e4m3x2 (b16); second source lands in the LOW byte
__device__ __forceinline__ unsigned short f8pack(float lo, float hi) {
    unsigned short r;
    asm("cvt.rn.satfinite.e4m3x2.f32 %0, %1, %2;" : "=h"(r) : "f"(hi), "f"(lo));
    return r;
}
// unpack 4 fp8 (one b32) -> 4 floats
__device__ __forceinline__ void f8x4_to_f(unsigned v, float2& a, float2& b) {
    unsigned short s0 = (unsigned short)(v & 0xffffu);
    unsigned short s1 = (unsigned short)(v >> 16);
    unsigned lo, hi;
    asm("cvt.rn.f16x2.e4m3x2 %0, %1;" : "=r"(lo) : "h"(s0));
    asm("cvt.rn.f16x2.e4m3x2 %0, %1;" : "=r"(hi) : "h"(s1));
    a = __half22float2(*(__half2*)&lo);
    b = __half22float2(*(__half2*)&hi);
}

// ---------------- init ----------------
__global__ void k_init() {
    int i = blockIdx.x * blockDim.x + threadIdx.x;
    if (i < N_NODES) g_deg[i] = 1;               // self loop
    if (i < N_GRAPHS * 64) g_pool[i] = 0.f;
}

// ---------------- fp32 -> half converts ----------------
__global__ void k_tohalf(const float* __restrict__ x) {
    int i = blockIdx.x * blockDim.x + threadIdx.x;   // one float4 -> 4 halves
    if (i >= N_NODES * 32) return;
    float4 v = *(const float4*)(x + (size_t)i * 4);
    __half2 h0 = __floats2half2_rn(v.x, v.y);
    __half2 h1 = __floats2half2_rn(v.z, v.w);
    uint2 o; o.x = *(unsigned*)&h0; o.y = *(unsigned*)&h1;
    *(uint2*)(g_hA + (size_t)i * 4) = o;
}

// all six W matrices in one kernel; i indexes half2 pairs (110592 total)
__global__ void k_wconv_all(const float* __restrict__ W1, const float* __restrict__ W2,
                            const float* __restrict__ W3, const float* __restrict__ W4,
                            const float* __restrict__ W5, const float* __restrict__ W6) {
    int i = blockIdx.x * blockDim.x + threadIdx.x;
    if (i >= 110592) return;
    const float* src;
    int off, loc;
    if (i < 16384)       { src = W1; off = OFF_W1; loc = i; }
    else if (i < 49152)  { src = W2; off = OFF_W2; loc = i - 16384; }
    else if (i < 81920)  { src = W3; off = OFF_W3; loc = i - 49152; }
    else if (i < 98304)  { src = W4; off = OFF_W4; loc = i - 81920; }
    else if (i < 106496) { src = W5; off = OFF_W5; loc = i - 98304; }
    else                 { src = W6; off = OFF_W6; loc = i - 106496; }
    float2 v = *(const float2*)(src + loc * 2);
    __half2 h = __floats2half2_rn(v.x, v.y);
    *(unsigned*)(g_Wh + off + loc * 2) = *(unsigned*)&h;
}

// ---------------- degree histogram over dst ----------------
__global__ void k_hist(const int* __restrict__ dst) {
    int i = blockIdx.x * blockDim.x + threadIdx.x;
    if (i < N_EDGES) atomicAdd(&g_deg[dst[i]], 1);
}

// ---------------- 3-phase multi-block exclusive scan of (deg-1) ----------------
__global__ void k_scan1() {
    __shared__ int ws[32];
    int t = threadIdx.x;
    int i = blockIdx.x * 1024 + t;
    int v = (i < N_NODES) ? (g_deg[i] - 1) : 0;
    int lane = t & 31, wid = t >> 5;
    int x = v;
#pragma unroll
    for (int off = 1; off < 32; off <<= 1) {
        int y = __shfl_up_sync(0xffffffffu, x, off);
        if (lane >= off) x += y;
    }
    if (lane == 31) ws[wid] = x;
    __syncthreads();
    if (wid == 0) {
        int s = ws[lane];
#pragma unroll
        for (int off = 1; off < 32; off <<= 1) {
            int y = __shfl_up_sync(0xffffffffu, s, off);
            if (lane >= off) s += y;
        }
        ws[lane] = s;
    }
    __syncthreads();
    int excl = (wid ? ws[wid - 1] : 0) + (x - v);
    if (i < N_NODES) g_rowptr[i] = excl;
    if (t == 0) g_bsum[blockIdx.x] = ws[31];
}

__global__ void k_scan2() {
    __shared__ int ws[4];
    int t = threadIdx.x;
    int v = (t < NBLK) ? g_bsum[t] : 0;
    int lane = t & 31, wid = t >> 5;
    int x = v;
#pragma unroll
    for (int off = 1; off < 32; off <<= 1) {
        int y = __shfl_up_sync(0xffffffffu, x, off);
        if (lane >= off) x += y;
    }
    if (lane == 31) ws[wid] = x;
    __syncthreads();
    int add = 0;
    for (int w = 0; w < wid; w++) add += ws[w];
    if (t < NBLK) g_bsum[t] = add + x - v;
}

__global__ void k_scan3() {
    int i = blockIdx.x * 1024 + threadIdx.x;
    if (i < N_NODES) {
        int v = g_rowptr[i] + g_bsum[blockIdx.x];
        g_rowptr[i] = v;
        g_cursor[i] = v;
        g_dinv[i] = rsqrtf((float)g_deg[i]);
    }
    if (i == 0) g_rowptr[N_NODES] = N_EDGES;
}

// fill CSR with packed (src, dinv[src]*dinv[dst])
__global__ void k_fill(const int* __restrict__ src, const int* __restrict__ dst) {
    int i = blockIdx.x * blockDim.x + threadIdx.x;
    if (i < N_EDGES) {
        int d = dst[i];
        int s = src[i];
        float w = g_dinv[s] * g_dinv[d];
        int p = atomicAdd(&g_cursor[d], 1);
        g_cw[p] = make_int2(s, __float_as_int(w));
    }
}

// ---------------- wmma GEMM: Out = A(half) @ Wh(half) + bias, relu; out half or fp8 ----------------
__global__ __launch_bounds__(256) void k_gemm(const __half* __restrict__ A,
                                              const __half* __restrict__ W,
                                              void* __restrict__ Out,
                                              int K, int Cn,
                                              const float* __restrict__ bias, int relu,
                                              int out_fp8) {
    __shared__ __half As[128][24];
    __shared__ __half Ws[16][72];
    __shared__ float  stage[8][1024];

    int tid = threadIdx.x;
    int wid = tid >> 5, lane = tid & 31;
    int wr = wid & 3, wc = wid >> 2;
    int row0 = blockIdx.y * 128, col0 = blockIdx.x * 64;

    wmma::fragment<wmma::accumulator, 16, 16, 16, float> fc[2][2];
#pragma unroll
    for (int i = 0; i < 2; i++)
#pragma unroll
        for (int j = 0; j < 2; j++) wmma::fill_fragment(fc[i][j], 0.f);

    int lr = tid >> 1, lp = tid & 1;
    int grow = row0 + lr;
    bool av = grow < N_NODES;
    const __half* Ap = A + (size_t)(av ? grow : 0) * K + lp * 8;

    for (int kk = 0; kk < K; kk += 16) {
        uint4 v = make_uint4(0u, 0u, 0u, 0u);
        if (av) v = *(const uint4*)(Ap + kk);
        *(uint4*)&As[lr][lp * 8] = v;
        if (tid < 128) {
            int r = tid >> 3, p = tid & 7;
            *(uint4*)&Ws[r][p * 8] =
                *(const uint4*)(W + (size_t)(kk + r) * Cn + col0 + p * 8);
        }
        __syncthreads();
        wmma::fragment<wmma::matrix_a, 16, 16, 16, __half, wmma::row_major> fa[2];
        wmma::fragment<wmma::matrix_b, 16, 16, 16, __half, wmma::row_major> fb[2];
        wmma::load_matrix_sync(fa[0], &As[wr * 32][0], 24);
        wmma::load_matrix_sync(fa[1], &As[wr * 32 + 16][0], 24);
        wmma::load_matrix_sync(fb[0], &Ws[0][wc * 32], 72);
        wmma::load_matrix_sync(fb[1], &Ws[0][wc * 32 + 16], 72);
#pragma unroll
        for (int i = 0; i < 2; i++)
#pragma unroll
            for (int j = 0; j < 2; j++)
                wmma::mma_sync(fc[i][j], fa[i], fb[j], fc[i][j]);
        __syncthreads();
    }

#pragma unroll
    for (int i = 0; i < 2; i++)
#pragma unroll
        for (int j = 0; j < 2; j++)
            wmma::store_matrix_sync(&stage[wid][(i * 16) * 32 + j * 16], fc[i][j], 32,
                                    wmma::mem_row_major);
    __syncwarp();

    int gr = row0 + wr * 32 + lane;
    if (gr < N_NODES) {
        int gc0 = col0 + wc * 32;
        const float* srow = &stage[wid][lane * 32];
#pragma unroll
        for (int q = 0; q < 4; q++) {
            float4 f0 = *(const float4*)(srow + q * 8);
            float4 f1 = *(const float4*)(srow + q * 8 + 4);
            float b[8] = {0, 0, 0, 0, 0, 0, 0, 0};
            if (bias) {
                float4 bb0 = *(const float4*)(bias + gc0 + q * 8);
                float4 bb1 = *(const float4*)(bias + gc0 + q * 8 + 4);
                b[0] = bb0.x; b[1] = bb0.y; b[2] = bb0.z; b[3] = bb0.w;
                b[4] = bb1.x; b[5] = bb1.y; b[6] = bb1.z; b[7] = bb1.w;
            }
            float r[8] = {f0.x + b[0], f0.y + b[1], f0.z + b[2], f0.w + b[3],
                          f1.x + b[4], f1.y + b[5], f1.z + b[6], f1.w + b[7]};
            if (relu) {
#pragma unroll
                for (int q2 = 0; q2 < 8; q2++) r[q2] = fmaxf(r[q2], 0.f);
            }
            if (out_fp8) {
                unsigned short s0 = f8pack(r[0], r[1]);
                unsigned short s1 = f8pack(r[2], r[3]);
                unsigned short s2 = f8pack(r[4], r[5]);
                unsigned short s3 = f8pack(r[6], r[7]);
                uint2 o;
                o.x = (unsigned)s0 | ((unsigned)s1 << 16);
                o.y = (unsigned)s2 | ((unsigned)s3 << 16);
                *(uint2*)((unsigned char*)Out + (size_t)gr * Cn + gc0 + q * 8) = o;
            } else {
                __half2 h0 = __floats2half2_rn(r[0], r[1]);
                __half2 h1 = __floats2half2_rn(r[2], r[3]);
                __half2 h2 = __floats2half2_rn(r[4], r[5]);
                __half2 h3 = __floats2half2_rn(r[6], r[7]);
                uint4 o;
                o.x = *(unsigned*)&h0; o.y = *(unsigned*)&h1;
                o.z = *(unsigned*)&h2; o.w = *(unsigned*)&h3;
                *(uint4*)((__half*)Out + (size_t)gr * Cn + gc0 + q * 8) = o;
            }
        }
    }
}

// ---------------- CSR aggregation: R6 inner loop; IN8 reads fp8 e4m3 ----------------
// channel half selected by blockIdx.y (choff = blockIdx.y * 128)
template <int CW, bool OUTF, bool IN8>
__global__ void k_agg(const void* __restrict__ Tptr, void* __restrict__ Optr,
                      const float* __restrict__ bias, int relu, int stride) {
    int warp = threadIdx.x >> 5;
    int lane = threadIdx.x & 31;
    int n = blockIdx.x * 8 + warp;
    int choff = blockIdx.y * 128;
    float dn = g_dinv[n];
    float dn2 = dn * dn;
    int s = g_rowptr[n], e = g_rowptr[n + 1];

    if (CW == 128) {
        int o0 = choff + lane * 4;
        const __half* Th = (const __half*)Tptr;
        const unsigned char* T8 = (const unsigned char*)Tptr;
        float2 f0, f1;
        if (IN8) {
            unsigned raw = *(const unsigned*)(T8 + (size_t)n * stride + o0);
            f8x4_to_f(raw, f0, f1);
        } else {
            uint2 raw = *(const uint2*)(Th + (size_t)n * stride + o0);
            f0 = __half22float2(*(__half2*)&raw.x);
            f1 = __half22float2(*(__half2*)&raw.y);
        }
        float ax = f0.x * dn2, ay = f0.y * dn2, az = f1.x * dn2, aw = f1.y * dn2;

        for (int base = s; base < e; base += 32) {
            int rem = e - base;
            int2 cw = make_int2(0, 0);
            if (lane < rem) cw = g_cw[base + lane];
            int nt = rem < 32 ? rem : 32;
            int t = 0;
            for (; t + 4 <= nt; t += 4) {
                int u0 = __shfl_sync(0xffffffffu, cw.x, t);
                int u1 = __shfl_sync(0xffffffffu, cw.x, t + 1);
                int u2 = __shfl_sync(0xffffffffu, cw.x, t + 2);
                int u3 = __shfl_sync(0xffffffffu, cw.x, t + 3);
                float w0 = __int_as_float(__shfl_sync(0xffffffffu, cw.y, t));
                float w1 = __int_as_float(__shfl_sync(0xffffffffu, cw.y, t + 1));
                float w2 = __int_as_float(__shfl_sync(0xffffffffu, cw.y, t + 2));
                float w3 = __int_as_float(__shfl_sync(0xffffffffu, cw.y, t + 3));
                if (IN8) {
                    unsigned r0 = *(const unsigned*)(T8 + (size_t)u0 * stride + o0);
                    unsigned r1 = *(const unsigned*)(T8 + (size_t)u1 * stride + o0);
                    unsigned r2 = *(const unsigned*)(T8 + (size_t)u2 * stride + o0);
                    unsigned r3 = *(const unsigned*)(T8 + (size_t)u3 * stride + o0);
                    float2 p0, p1, q0, q1, s0, s1, v0, v1;
                    f8x4_to_f(r0, p0, p1);
                    f8x4_to_f(r1, q0, q1);
                    f8x4_to_f(r2, s0, s1);
                    f8x4_to_f(r3, v0, v1);
                    ax += w0 * p0.x + w1 * q0.x + w2 * s0.x + w3 * v0.x;
                    ay += w0 * p0.y + w1 * q0.y + w2 * s0.y + w3 * v0.y;
                    az += w0 * p1.x + w1 * q1.x + w2 * s1.x + w3 * v1.x;
                    aw += w0 * p1.y + w1 * q1.y + w2 * s1.y + w3 * v1.y;
                } else {
                    uint2 r0 = *(const uint2*)(Th + (size_t)u0 * stride + o0);
                    uint2 r1 = *(const uint2*)(Th + (size_t)u1 * stride + o0);
                    uint2 r2 = *(const uint2*)(Th + (size_t)u2 * stride + o0);
                    uint2 r3 = *(const uint2*)(Th + (size_t)u3 * stride + o0);
                    float2 p0 = __half22float2(*(__half2*)&r0.x), p1 = __half22float2(*(__half2*)&r0.y);
                    float2 q0 = __half22float2(*(__half2*)&r1.x), q1 = __half22float2(*(__half2*)&r1.y);
                    float2 s0 = __half22float2(*(__half2*)&r2.x), s1 = __half22float2(*(__half2*)&r2.y);
                    float2 v0 = __half22float2(*(__half2*)&r3.x), v1 = __half22float2(*(__half2*)&r3.y);
                    ax += w0 * p0.x + w1 * q0.x + w2 * s0.x + w3 * v0.x;
                    ay += w0 * p0.y + w1 * q0.y + w2 * s0.y + w3 * v0.y;
                    az += w0 * p1.x + w1 * q1.x + w2 * s1.x + w3 * v1.x;
                    aw += w0 * p1.y + w1 * q1.y + w2 * s1.y + w3 * v1.y;
                }
            }
            for (; t < nt; t++) {
                int u = __shfl_sync(0xffffffffu, cw.x, t);
                float w = __int_as_float(__shfl_sync(0xffffffffu, cw.y, t));
                float2 p0, p1;
                if (IN8) {
                    unsigned r0 = *(const unsigned*)(T8 + (size_t)u * stride + o0);
                    f8x4_to_f(r0, p0, p1);
                } else {
                    uint2 r0 = *(const uint2*)(Th + (size_t)u * stride + o0);
                    p0 = __half22float2(*(__half2*)&r0.x);
                    p1 = __half22float2(*(__half2*)&r0.y);
                }
                ax += w * p0.x; ay += w * p0.y; az += w * p1.x; aw += w * p1.y;
            }
        }
        float4 b0 = make_float4(0.f, 0.f, 0.f, 0.f);
        if (bias) b0 = *(const float4*)(bias + o0);
        float rx = ax + b0.x, ry = ay + b0.y, rz = az + b0.z, rw = aw + b0.w;
        if (relu) {
            rx = fmaxf(rx, 0.f); ry = fmaxf(ry, 0.f);
            rz = fmaxf(rz, 0.f); rw = fmaxf(rw, 0.f);
        }
        if (OUTF) {
            *(float4*)((float*)Optr + (size_t)n * stride + o0) = make_float4(rx, ry, rz, rw);
        } else {
            __half2 p0 = __floats2half2_rn(rx, ry);
            __half2 p1 = __floats2half2_rn(rz, rw);
            uint2 o; o.x = *(unsigned*)&p0; o.y = *(unsigned*)&p1;
            *(uint2*)((__half*)Optr + (size_t)n * stride + o0) = o;
        }
    } else { // CW == 64, half input only
        int o0 = choff + lane * 2;
        const __half* Th = (const __half*)Tptr;
        unsigned raw = *(const unsigned*)(Th + (size_t)n * stride + o0);
        float2 f0 = __half22float2(*(__half2*)&raw);
        float ax = f0.x * dn2, ay = f0.y * dn2;
        for (int base = s; base < e; base += 32) {
            int rem = e - base;
            int2 cw = make_int2(0, 0);
            if (lane < rem) cw = g_cw[base + lane];
            int nt = rem < 32 ? rem : 32;
            int t = 0;
            for (; t + 4 <= nt; t += 4) {
                int u0 = __shfl_sync(0xffffffffu, cw.x, t);
                int u1 = __shfl_sync(0xffffffffu, cw.x, t + 1);
                int u2 = __shfl_sync(0xffffffffu, cw.x, t + 2);
                int u3 = __shfl_sync(0xffffffffu, cw.x, t + 3);
                float w0 = __int_as_float(__shfl_sync(0xffffffffu, cw.y, t));
                float w1 = __int_as_float(__shfl_sync(0xffffffffu, cw.y, t + 1));
                float w2 = __int_as_float(__shfl_sync(0xffffffffu, cw.y, t + 2));
                float w3 = __int_as_float(__shfl_sync(0xffffffffu, cw.y, t + 3));
                unsigned r0 = *(const unsigned*)(Th + (size_t)u0 * stride + o0);
                unsigned r1 = *(const unsigned*)(Th + (size_t)u1 * stride + o0);
                unsigned r2 = *(const unsigned*)(Th + (size_t)u2 * stride + o0);
                unsigned r3 = *(const unsigned*)(Th + (size_t)u3 * stride + o0);
                float2 p0 = __half22float2(*(__half2*)&r0);
                float2 p1 = __half22float2(*(__half2*)&r1);
                float2 p2 = __half22float2(*(__half2*)&r2);
                float2 p3 = __half22float2(*(__half2*)&r3);
                ax += w0 * p0.x + w1 * p1.x + w2 * p2.x + w3 * p3.x;
                ay += w0 * p0.y + w1 * p1.y + w2 * p2.y + w3 * p3.y;
            }
            for (; t < nt; t++) {
                int u = __shfl_sync(0xffffffffu, cw.x, t);
                float w = __int_as_float(__shfl_sync(0xffffffffu, cw.y, t));
                unsigned r0 = *(const unsigned*)(Th + (size_t)u * stride + o0);
                float2 p0 = __half22float2(*(__half2*)&r0);
                ax += w * p0.x; ay += w * p0.y;
            }
        }
        float2 b0 = make_float2(0.f, 0.f);
        if (bias) b0 = *(const float2*)(bias + o0);
        float rx = ax + b0.x, ry = ay + b0.y;
        if (relu) { rx = fmaxf(rx, 0.f); ry = fmaxf(ry, 0.f); }
        if (OUTF) {
            *(float2*)((float*)Optr + (size_t)n * stride + o0) = make_float2(rx, ry);
        } else {
            __half2 p0 = __floats2half2_rn(rx, ry);
            *(unsigned*)((__half*)Optr + (size_t)n * stride + o0) = *(unsigned*)&p0;
        }
    }
}

// ---------------- pooling: run-length accumulate over 8 consecutive nodes ----------------
__global__ void k_pool(const float* __restrict__ h, const int* __restrict__ batch) {
    int idx = blockIdx.x * blockDim.x + threadIdx.x;
    if (idx >= (N_NODES / 8) * 16) return;
    int grp = idx >> 4, q = idx & 15;
    int n0 = grp * 8;
    float4 acc = make_float4(0.f, 0.f, 0.f, 0.f);
    int curg = batch[n0];
#pragma unroll
    for (int i = 0; i < 8; i++) {
        int n = n0 + i;
        int g = batch[n];
        float4 v = *(const float4*)(h + (size_t)n * 64 + q * 4);
        if (g != curg) {
            float* p = g_pool + curg * 64 + q * 4;
            atomicAdd(p + 0, acc.x); atomicAdd(p + 1, acc.y);
            atomicAdd(p + 2, acc.z); atomicAdd(p + 3, acc.w);
            acc = make_float4(0.f, 0.f, 0.f, 0.f);
            curg = g;
        }
        acc.x += v.x; acc.y += v.y; acc.z += v.z; acc.w += v.w;
    }
    float* p = g_pool + curg * 64 + q * 4;
    atomicAdd(p + 0, acc.x); atomicAdd(p + 1, acc.y);
    atomicAdd(p + 2, acc.z); atomicAdd(p + 3, acc.w);
}

// ---------------- counts via binary search over sorted batch ----------------
__global__ void k_cnt(const int* __restrict__ batch) {
    int g = blockIdx.x * blockDim.x + threadIdx.x;
    if (g >= N_GRAPHS) return;
    int lo = 0, hi = N_NODES;
    while (lo < hi) { int m = (lo + hi) >> 1; if (batch[m] < g) lo = m + 1; else hi = m; }
    int a = lo;
    lo = a; hi = N_NODES;
    while (lo < hi) { int m = (lo + hi) >> 1; if (batch[m] < g + 1) lo = m + 1; else hi = m; }
    g_cnt[g] = lo - a;
}

// ---------------- head ----------------
__global__ void k_final(const float* __restrict__ Wlin, const float* __restrict__ blin,
                        float* __restrict__ out) {
    int g = blockIdx.x;
    int t = threadIdx.x;  // 64 threads
    __shared__ float mean[64];
    __shared__ float logits[10];
    __shared__ float red2[2];
    float c = (float)g_cnt[g];
    float inv = 1.0f / fmaxf(c, 1.0f);
    mean[t] = g_pool[g * 64 + t] * inv;
    __syncthreads();
    if (t < 10) {
        float s = blin[t];
        for (int k = 0; k < 64; k++) s += mean[k] * Wlin[k * 10 + t];
        logits[t] = s;
    }
    __syncthreads();
    if (t == 0) {
        float mx = logits[0];
        for (int l = 1; l < 10; l++) mx = fmaxf(mx, logits[l]);
        float se = 0.f;
        for (int l = 0; l < 10; l++) se += expf(logits[l] - mx);
        red2[0] = mx;
        red2[1] = se;
    }
    __syncthreads();
    if (t < 10) {
        float lsm = logits[t] - red2[0] - logf(red2[1]);
        out[g * 10 + t] = lsm;
        out[N_GRAPHS * 10 + g * 10 + t] = expf(lsm);
    }
}

// ---------------- launch ----------------
extern "C" void kernel_launch(void* const* d_in, const int* in_sizes, int n_in,
                              void* d_out, int out_size) {
    const float* x     = (const float*)d_in[0];
    const int*   ei    = (const int*)d_in[1];
    const int*   batch = (const int*)d_in[2];
    const float* W1 = (const float*)d_in[4];  const float* b1 = (const float*)d_in[5];
    const float* W2 = (const float*)d_in[6];  const float* b2 = (const float*)d_in[7];
    const float* W3 = (const float*)d_in[8];  const float* b3 = (const float*)d_in[9];
    const float* W4 = (const float*)d_in[10]; const float* b4 = (const float*)d_in[11];
    const float* W5 = (const float*)d_in[12]; const float* b5 = (const float*)d_in[13];
    const float* W6 = (const float*)d_in[14]; const float* b6 = (const float*)d_in[15];
    const float* Wlin = (const float*)d_in[16];
    const float* blin = (const float*)d_in[17];
    const int* src = ei;
    const int* dst = ei + N_EDGES;
    float* out = (float*)d_out;

    __half *hA, *hB, *Wh;
    unsigned char *q8;
    float *h6;
    cudaGetSymbolAddress((void**)&hA, g_hA);
    cudaGetSymbolAddress((void**)&hB, g_hB);
    cudaGetSymbolAddress((void**)&q8, g_q8);
    cudaGetSymbolAddress((void**)&h6, g_h6);
    cudaGetSymbolAddress((void**)&Wh, g_Wh);

    const int TB = 256;
    int gN = (N_NODES + TB - 1) / TB;
    int gE = (N_EDGES + TB - 1) / TB;

    // preprocessing (+ converts)
    k_init<<<gN, TB>>>();
    k_tohalf<<<(N_NODES * 32 + TB - 1) / TB, TB>>>(x);
    k_wconv_all<<<(110592 + TB - 1) / TB, TB>>>(W1, W2, W3, W4, W5, W6);
    k_hist<<<gE, TB>>>(dst);
    k_scan1<<<NBLK, 1024>>>();
    k_scan2<<<1, 128>>>();
    k_scan3<<<NBLK, 1024>>>();
    k_fill<<<gE, TB>>>(src, dst);
    k_cnt<<<2, 256>>>(batch);

    int aggBlocks = N_NODES / 8;
    dim3 agg1(aggBlocks, 1), agg2(aggBlocks, 2);
    dim3 g256(4, 782), g128(2, 782), g64(1, 782);

    // L1: aggregate-first (128 ch) on half x, then GEMM 128->256 (+bias+relu)
    k_agg<128, false, false><<<agg1, 256>>>(hA, hB, nullptr, 0, 128);
    k_gemm<<<g256, 256>>>(hB, Wh + OFF_W1, hA, 128, 256, b1, 1, 0);
    // L2: transform-first -> fp8, agg reads fp8 (both halves, gridDim.y=2)
    k_gemm<<<g256, 256>>>(hA, Wh + OFF_W2, q8, 256, 256, nullptr, 0, 1);
    k_agg<128, false, true><<<agg2, 256>>>(q8, hA, b2, 1, 256);
    // L3
    k_gemm<<<g256, 256>>>(hA, Wh + OFF_W3, q8, 256, 256, nullptr, 0, 1);
    k_agg<128, false, true><<<agg2, 256>>>(q8, hA, b3, 1, 256);
    // L4: 256->128 (half)
    k_gemm<<<g128, 256>>>(hA, Wh + OFF_W4, hB, 256, 128, nullptr, 0, 0);
    k_agg<128, false, false><<<agg1, 256>>>(hB, hA, b4, 1, 128);
    // L5: 128->128
    k_gemm<<<g128, 256>>>(hA, Wh + OFF_W5, hB, 128, 128, nullptr, 0, 0);
    k_agg<128, false, false><<<agg1, 256>>>(hB, hA, b5, 1, 128);
    // L6: 128->64, no relu; agg writes fp32 for pooling
    k_gemm<<<g64, 256>>>(hA, Wh + OFF_W6, hB, 128, 64, nullptr, 0, 0);
    k_agg<64, true, false><<<agg1, 256>>>(hB, h6, b6, 0, 64);

    // pooling + head
    k_pool<<<((N_NODES / 8) * 16 + TB - 1) / TB, TB>>>(h6, batch);
    k_final<<<N_GRAPHS, 64>>>(Wlin, blin, out);
}

// round 16
// speedup vs baseline: 1.1876x; 1.0389x over previous
#include <cuda_runtime.h>
#include <cuda_fp16.h>
#include <mma.h>
#include <math.h>

using namespace nvcuda;

#define N_NODES  100000
#define N_EDGES  3200000
#define N_GRAPHS 512
#define NBLK     98          // ceil(100000/1024)

// ---------------- scratch (static device globals; no allocation) ----------------
__device__ __half g_hA[(size_t)N_NODES * 256];
__device__ __half g_hB[(size_t)N_NODES * 256];
__device__ unsigned char g_q8[(size_t)N_NODES * 256];  // fp8 e4m3 activations
__device__ float  g_h6[(size_t)N_NODES * 64];   // final layer output (fp32 for pooling)
__device__ __half g_Wh[262144];                 // all W matrices in half (offsets below)
__device__ int    g_deg[N_NODES];
__device__ float  g_dinv[N_NODES];
__device__ int    g_rowptr[N_NODES + 1];
__device__ int    g_cursor[N_NODES];
__device__ int2   g_cw[N_EDGES];                // packed (src, weight)
__device__ int    g_bsum[128];
__device__ float  g_pool[N_GRAPHS * 64];
__device__ int    g_cnt[N_GRAPHS];

// W offsets in g_Wh (half elements)
#define OFF_W1 0           // 128*256 = 32768
#define OFF_W2 32768       // 256*256 = 65536
#define OFF_W3 98304       // 65536
#define OFF_W4 163840      // 256*128 = 32768
#define OFF_W5 196608      // 128*128 = 16384
#define OFF_W6 212992      // 128*64  = 8192

// ---------------- fp8 helpers ----------------
__device__ __forceinline__ unsigned short f8pack(float lo, float hi) {
    unsigned short r;
    asm("cvt.rn.satfinite.e4m3x2.f32 %0, %1, %2;" : "=h"(r) : "f"(hi), "f"(lo));
    return r;
}
__device__ __forceinline__ void f8x4_to_f(unsigned v, float2& a, float2& b) {
    unsigned short s0 = (unsigned short)(v & 0xffffu);
    unsigned short s1 = (unsigned short)(v >> 16);
    unsigned lo, hi;
    asm("cvt.rn.f16x2.e4m3x2 %0, %1;" : "=r"(lo) : "h"(s0));
    asm("cvt.rn.f16x2.e4m3x2 %0, %1;" : "=r"(hi) : "h"(s1));
    a = __half22float2(*(__half2*)&lo);
    b = __half22float2(*(__half2*)&hi);
}

// ---------------- init ----------------
__global__ void k_init() {
    int i = blockIdx.x * blockDim.x + threadIdx.x;
    if (i < N_NODES) g_deg[i] = 1;               // self loop
    if (i < N_GRAPHS * 64) g_pool[i] = 0.f;
}

// ---------------- fp32 -> half converts ----------------
__global__ void k_tohalf(const float* __restrict__ x) {
    int i = blockIdx.x * blockDim.x + threadIdx.x;   // one float4 -> 4 halves
    if (i >= N_NODES * 32) return;
    float4 v = *(const float4*)(x + (size_t)i * 4);
    __half2 h0 = __floats2half2_rn(v.x, v.y);
    __half2 h1 = __floats2half2_rn(v.z, v.w);
    uint2 o; o.x = *(unsigned*)&h0; o.y = *(unsigned*)&h1;
    *(uint2*)(g_hA + (size_t)i * 4) = o;
}

// all six W matrices in one kernel; i indexes half2 pairs (110592 total)
__global__ void k_wconv_all(const float* __restrict__ W1, const float* __restrict__ W2,
                            const float* __restrict__ W3, const float* __restrict__ W4,
                            const float* __restrict__ W5, const float* __restrict__ W6) {
    int i = blockIdx.x * blockDim.x + threadIdx.x;
    if (i >= 110592) return;
    const float* src;
    int off, loc;
    if (i < 16384)       { src = W1; off = OFF_W1; loc = i; }
    else if (i < 49152)  { src = W2; off = OFF_W2; loc = i - 16384; }
    else if (i < 81920)  { src = W3; off = OFF_W3; loc = i - 49152; }
    else if (i < 98304)  { src = W4; off = OFF_W4; loc = i - 81920; }
    else if (i < 106496) { src = W5; off = OFF_W5; loc = i - 98304; }
    else                 { src = W6; off = OFF_W6; loc = i - 106496; }
    float2 v = *(const float2*)(src + loc * 2);
    __half2 h = __floats2half2_rn(v.x, v.y);
    *(unsigned*)(g_Wh + off + loc * 2) = *(unsigned*)&h;
}

// ---------------- degree histogram over dst ----------------
__global__ void k_hist(const int* __restrict__ dst) {
    int i = blockIdx.x * blockDim.x + threadIdx.x;
    if (i < N_EDGES) atomicAdd(&g_deg[dst[i]], 1);
}

// ---------------- 3-phase multi-block exclusive scan of (deg-1) ----------------
__global__ void k_scan1() {
    __shared__ int ws[32];
    int t = threadIdx.x;
    int i = blockIdx.x * 1024 + t;
    int v = (i < N_NODES) ? (g_deg[i] - 1) : 0;
    int lane = t & 31, wid = t >> 5;
    int x = v;
#pragma unroll
    for (int off = 1; off < 32; off <<= 1) {
        int y = __shfl_up_sync(0xffffffffu, x, off);
        if (lane >= off) x += y;
    }
    if (lane == 31) ws[wid] = x;
    __syncthreads();
    if (wid == 0) {
        int s = ws[lane];
#pragma unroll
        for (int off = 1; off < 32; off <<= 1) {
            int y = __shfl_up_sync(0xffffffffu, s, off);
            if (lane >= off) s += y;
        }
        ws[lane] = s;
    }
    __syncthreads();
    int excl = (wid ? ws[wid - 1] : 0) + (x - v);
    if (i < N_NODES) g_rowptr[i] = excl;
    if (t == 0) g_bsum[blockIdx.x] = ws[31];
}

__global__ void k_scan2() {
    __shared__ int ws[4];
    int t = threadIdx.x;
    int v = (t < NBLK) ? g_bsum[t] : 0;
    int lane = t & 31, wid = t >> 5;
    int x = v;
#pragma unroll
    for (int off = 1; off < 32; off <<= 1) {
        int y = __shfl_up_sync(0xffffffffu, x, off);
        if (lane >= off) x += y;
    }
    if (lane == 31) ws[wid] = x;
    __syncthreads();
    int add = 0;
    for (int w = 0; w < wid; w++) add += ws[w];
    if (t < NBLK) g_bsum[t] = add + x - v;
}

__global__ void k_scan3() {
    int i = blockIdx.x * 1024 + threadIdx.x;
    if (i < N_NODES) {
        int v = g_rowptr[i] + g_bsum[blockIdx.x];
        g_rowptr[i] = v;
        g_cursor[i] = v;
        g_dinv[i] = rsqrtf((float)g_deg[i]);
    }
    if (i == 0) g_rowptr[N_NODES] = N_EDGES;
}

// fill CSR with packed (src, dinv[src]*dinv[dst])
__global__ void k_fill(const int* __restrict__ src, const int* __restrict__ dst) {
    int i = blockIdx.x * blockDim.x + threadIdx.x;
    if (i < N_EDGES) {
        int d = dst[i];
        int s = src[i];
        float w = g_dinv[s] * g_dinv[d];
        int p = atomicAdd(&g_cursor[d], 1);
        g_cw[p] = make_int2(s, __float_as_int(w));
    }
}

// ---------------- wmma GEMM: Out = A(half) @ Wh(half) + bias, relu; out half or fp8 ----------------
__global__ __launch_bounds__(256) void k_gemm(const __half* __restrict__ A,
                                              const __half* __restrict__ W,
                                              void* __restrict__ Out,
                                              int K, int Cn,
                                              const float* __restrict__ bias, int relu,
                                              int out_fp8) {
    __shared__ __half As[128][24];
    __shared__ __half Ws[16][72];
    __shared__ float  stage[8][1024];

    int tid = threadIdx.x;
    int wid = tid >> 5, lane = tid & 31;
    int wr = wid & 3, wc = wid >> 2;
    int row0 = blockIdx.y * 128, col0 = blockIdx.x * 64;

    wmma::fragment<wmma::accumulator, 16, 16, 16, float> fc[2][2];
#pragma unroll
    for (int i = 0; i < 2; i++)
#pragma unroll
        for (int j = 0; j < 2; j++) wmma::fill_fragment(fc[i][j], 0.f);

    int lr = tid >> 1, lp = tid & 1;
    int grow = row0 + lr;
    bool av = grow < N_NODES;
    const __half* Ap = A + (size_t)(av ? grow : 0) * K + lp * 8;

    for (int kk = 0; kk < K; kk += 16) {
        uint4 v = make_uint4(0u, 0u, 0u, 0u);
        if (av) v = *(const uint4*)(Ap + kk);
        *(uint4*)&As[lr][lp * 8] = v;
        if (tid < 128) {
            int r = tid >> 3, p = tid & 7;
            *(uint4*)&Ws[r][p * 8] =
                *(const uint4*)(W + (size_t)(kk + r) * Cn + col0 + p * 8);
        }
        __syncthreads();
        wmma::fragment<wmma::matrix_a, 16, 16, 16, __half, wmma::row_major> fa[2];
        wmma::fragment<wmma::matrix_b, 16, 16, 16, __half, wmma::row_major> fb[2];
        wmma::load_matrix_sync(fa[0], &As[wr * 32][0], 24);
        wmma::load_matrix_sync(fa[1], &As[wr * 32 + 16][0], 24);
        wmma::load_matrix_sync(fb[0], &Ws[0][wc * 32], 72);
        wmma::load_matrix_sync(fb[1], &Ws[0][wc * 32 + 16], 72);
#pragma unroll
        for (int i = 0; i < 2; i++)
#pragma unroll
            for (int j = 0; j < 2; j++)
                wmma::mma_sync(fc[i][j], fa[i], fb[j], fc[i][j]);
        __syncthreads();
    }

#pragma unroll
    for (int i = 0; i < 2; i++)
#pragma unroll
        for (int j = 0; j < 2; j++)
            wmma::store_matrix_sync(&stage[wid][(i * 16) * 32 + j * 16], fc[i][j], 32,
                                    wmma::mem_row_major);
    __syncwarp();

    int gr = row0 + wr * 32 + lane;
    if (gr < N_NODES) {
        int gc0 = col0 + wc * 32;
        const float* srow = &stage[wid][lane * 32];
#pragma unroll
        for (int q = 0; q < 4; q++) {
            float4 f0 = *(const float4*)(srow + q * 8);
            float4 f1 = *(const float4*)(srow + q * 8 + 4);
            float b[8] = {0, 0, 0, 0, 0, 0, 0, 0};
            if (bias) {
                float4 bb0 = *(const float4*)(bias + gc0 + q * 8);
                float4 bb1 = *(const float4*)(bias + gc0 + q * 8 + 4);
                b[0] = bb0.x; b[1] = bb0.y; b[2] = bb0.z; b[3] = bb0.w;
                b[4] = bb1.x; b[5] = bb1.y; b[6] = bb1.z; b[7] = bb1.w;
            }
            float r[8] = {f0.x + b[0], f0.y + b[1], f0.z + b[2], f0.w + b[3],
                          f1.x + b[4], f1.y + b[5], f1.z + b[6], f1.w + b[7]};
            if (relu) {
#pragma unroll
                for (int q2 = 0; q2 < 8; q2++) r[q2] = fmaxf(r[q2], 0.f);
            }
            if (out_fp8) {
                unsigned short s0 = f8pack(r[0], r[1]);
                unsigned short s1 = f8pack(r[2], r[3]);
                unsigned short s2 = f8pack(r[4], r[5]);
                unsigned short s3 = f8pack(r[6], r[7]);
                uint2 o;
                o.x = (unsigned)s0 | ((unsigned)s1 << 16);
                o.y = (unsigned)s2 | ((unsigned)s3 << 16);
                *(uint2*)((unsigned char*)Out + (size_t)gr * Cn + gc0 + q * 8) = o;
            } else {
                __half2 h0 = __floats2half2_rn(r[0], r[1]);
                __half2 h1 = __floats2half2_rn(r[2], r[3]);
                __half2 h2 = __floats2half2_rn(r[4], r[5]);
                __half2 h3 = __floats2half2_rn(r[6], r[7]);
                uint4 o;
                o.x = *(unsigned*)&h0; o.y = *(unsigned*)&h1;
                o.z = *(unsigned*)&h2; o.w = *(unsigned*)&h3;
                *(uint4*)((__half*)Out + (size_t)gr * Cn + gc0 + q * 8) = o;
            }
        }
    }
}

// ---------------- CSR aggregation (R6-form loop) ----------------
// CW=256: fp8 input only, FULL width in one pass (8B/lane).
// CW=128: fp8 (4B/lane) or half (8B/lane). CW=64: half.
template <int CW, bool OUTF, bool IN8>
__global__ void k_agg(const void* __restrict__ Tptr, void* __restrict__ Optr,
                      const float* __restrict__ bias, int relu, int stride) {
    int warp = threadIdx.x >> 5;
    int lane = threadIdx.x & 31;
    int n = blockIdx.x * 8 + warp;
    float dn = g_dinv[n];
    float dn2 = dn * dn;
    int s = g_rowptr[n], e = g_rowptr[n + 1];

    if (CW == 256) {   // fp8, single pass over full 256 channels
        int o0 = lane * 8;   // byte offset (8 fp8 per lane)
        const unsigned char* T8 = (const unsigned char*)Tptr;
        uint2 rawv = *(const uint2*)(T8 + (size_t)n * stride + o0);
        float2 f0, f1, f2, f3;
        f8x4_to_f(rawv.x, f0, f1);
        f8x4_to_f(rawv.y, f2, f3);
        float a0 = f0.x * dn2, a1 = f0.y * dn2, a2 = f1.x * dn2, a3 = f1.y * dn2;
        float a4 = f2.x * dn2, a5 = f2.y * dn2, a6 = f3.x * dn2, a7 = f3.y * dn2;

        for (int base = s; base < e; base += 32) {
            int rem = e - base;
            int2 cw = make_int2(0, 0);
            if (lane < rem) cw = g_cw[base + lane];
            int nt = rem < 32 ? rem : 32;
            int t = 0;
            for (; t + 2 <= nt; t += 2) {
                int u0 = __shfl_sync(0xffffffffu, cw.x, t);
                int u1 = __shfl_sync(0xffffffffu, cw.x, t + 1);
                float w0 = __int_as_float(__shfl_sync(0xffffffffu, cw.y, t));
                float w1 = __int_as_float(__shfl_sync(0xffffffffu, cw.y, t + 1));
                uint2 r0 = *(const uint2*)(T8 + (size_t)u0 * stride + o0);
                uint2 r1 = *(const uint2*)(T8 + (size_t)u1 * stride + o0);
                float2 p0, p1, p2, p3, q0, q1, q2, q3;
                f8x4_to_f(r0.x, p0, p1); f8x4_to_f(r0.y, p2, p3);
                f8x4_to_f(r1.x, q0, q1); f8x4_to_f(r1.y, q2, q3);
                a0 += w0 * p0.x + w1 * q0.x;  a1 += w0 * p0.y + w1 * q0.y;
                a2 += w0 * p1.x + w1 * q1.x;  a3 += w0 * p1.y + w1 * q1.y;
                a4 += w0 * p2.x + w1 * q2.x;  a5 += w0 * p2.y + w1 * q2.y;
                a6 += w0 * p3.x + w1 * q3.x;  a7 += w0 * p3.y + w1 * q3.y;
            }
            if (t < nt) {
                int u = __shfl_sync(0xffffffffu, cw.x, t);
                float w = __int_as_float(__shfl_sync(0xffffffffu, cw.y, t));
                uint2 r0 = *(const uint2*)(T8 + (size_t)u * stride + o0);
                float2 p0, p1, p2, p3;
                f8x4_to_f(r0.x, p0, p1); f8x4_to_f(r0.y, p2, p3);
                a0 += w * p0.x; a1 += w * p0.y; a2 += w * p1.x; a3 += w * p1.y;
                a4 += w * p2.x; a5 += w * p2.y; a6 += w * p3.x; a7 += w * p3.y;
            }
        }
        float r[8] = {a0, a1, a2, a3, a4, a5, a6, a7};
        if (bias) {
            float4 b0 = *(const float4*)(bias + o0);
            float4 b1 = *(const float4*)(bias + o0 + 4);
            r[0] += b0.x; r[1] += b0.y; r[2] += b0.z; r[3] += b0.w;
            r[4] += b1.x; r[5] += b1.y; r[6] += b1.z; r[7] += b1.w;
        }
        if (relu) {
#pragma unroll
            for (int q = 0; q < 8; q++) r[q] = fmaxf(r[q], 0.f);
        }
        __half2 h0 = __floats2half2_rn(r[0], r[1]);
        __half2 h1 = __floats2half2_rn(r[2], r[3]);
        __half2 h2 = __floats2half2_rn(r[4], r[5]);
        __half2 h3 = __floats2half2_rn(r[6], r[7]);
        uint4 o;
        o.x = *(unsigned*)&h0; o.y = *(unsigned*)&h1;
        o.z = *(unsigned*)&h2; o.w = *(unsigned*)&h3;
        *(uint4*)((__half*)Optr + (size_t)n * stride + o0) = o;
    } else if (CW == 128) {
        int o0 = lane * 4;
        const __half* Th = (const __half*)Tptr;
        const unsigned char* T8 = (const unsigned char*)Tptr;
        float2 f0, f1;
        if (IN8) {
            unsigned raw = *(const unsigned*)(T8 + (size_t)n * stride + o0);
            f8x4_to_f(raw, f0, f1);
        } else {
            uint2 raw = *(const uint2*)(Th + (size_t)n * stride + o0);
            f0 = __half22float2(*(__half2*)&raw.x);
            f1 = __half22float2(*(__half2*)&raw.y);
        }
        float ax = f0.x * dn2, ay = f0.y * dn2, az = f1.x * dn2, aw = f1.y * dn2;

        for (int base = s; base < e; base += 32) {
            int rem = e - base;
            int2 cw = make_int2(0, 0);
            if (lane < rem) cw = g_cw[base + lane];
            int nt = rem < 32 ? rem : 32;
            int t = 0;
            for (; t + 4 <= nt; t += 4) {
                int u0 = __shfl_sync(0xffffffffu, cw.x, t);
                int u1 = __shfl_sync(0xffffffffu, cw.x, t + 1);
                int u2 = __shfl_sync(0xffffffffu, cw.x, t + 2);
                int u3 = __shfl_sync(0xffffffffu, cw.x, t + 3);
                float w0 = __int_as_float(__shfl_sync(0xffffffffu, cw.y, t));
                float w1 = __int_as_float(__shfl_sync(0xffffffffu, cw.y, t + 1));
                float w2 = __int_as_float(__shfl_sync(0xffffffffu, cw.y, t + 2));
                float w3 = __int_as_float(__shfl_sync(0xffffffffu, cw.y, t + 3));
                if (IN8) {
                    unsigned r0 = *(const unsigned*)(T8 + (size_t)u0 * stride + o0);
                    unsigned r1 = *(const unsigned*)(T8 + (size_t)u1 * stride + o0);
                    unsigned r2 = *(const unsigned*)(T8 + (size_t)u2 * stride + o0);
                    unsigned r3 = *(const unsigned*)(T8 + (size_t)u3 * stride + o0);
                    float2 p0, p1, q0, q1, s0, s1, v0, v1;
                    f8x4_to_f(r0, p0, p1);
                    f8x4_to_f(r1, q0, q1);
                    f8x4_to_f(r2, s0, s1);
                    f8x4_to_f(r3, v0, v1);
                    ax += w0 * p0.x + w1 * q0.x + w2 * s0.x + w3 * v0.x;
                    ay += w0 * p0.y + w1 * q0.y + w2 * s0.y + w3 * v0.y;
                    az += w0 * p1.x + w1 * q1.x + w2 * s1.x + w3 * v1.x;
                    aw += w0 * p1.y + w1 * q1.y + w2 * s1.y + w3 * v1.y;
                } else {
                    uint2 r0 = *(const uint2*)(Th + (size_t)u0 * stride + o0);
                    uint2 r1 = *(const uint2*)(Th + (size_t)u1 * stride + o0);
                    uint2 r2 = *(const uint2*)(Th + (size_t)u2 * stride + o0);
                    uint2 r3 = *(const uint2*)(Th + (size_t)u3 * stride + o0);
                    float2 p0 = __half22float2(*(__half2*)&r0.x), p1 = __half22float2(*(__half2*)&r0.y);
                    float2 q0 = __half22float2(*(__half2*)&r1.x), q1 = __half22float2(*(__half2*)&r1.y);
                    float2 s0 = __half22float2(*(__half2*)&r2.x), s1 = __half22float2(*(__half2*)&r2.y);
                    float2 v0 = __half22float2(*(__half2*)&r3.x), v1 = __half22float2(*(__half2*)&r3.y);
                    ax += w0 * p0.x + w1 * q0.x + w2 * s0.x + w3 * v0.x;
                    ay += w0 * p0.y + w1 * q0.y + w2 * s0.y + w3 * v0.y;
                    az += w0 * p1.x + w1 * q1.x + w2 * s1.x + w3 * v1.x;
                    aw += w0 * p1.y + w1 * q1.y + w2 * s1.y + w3 * v1.y;
                }
            }
            for (; t < nt; t++) {
                int u = __shfl_sync(0xffffffffu, cw.x, t);
                float w = __int_as_float(__shfl_sync(0xffffffffu, cw.y, t));
                float2 p0, p1;
                if (IN8) {
                    unsigned r0 = *(const unsigned*)(T8 + (size_t)u * stride + o0);
                    f8x4_to_f(r0, p0, p1);
                } else {
                    uint2 r0 = *(const uint2*)(Th + (size_t)u * stride + o0);
                    p0 = __half22float2(*(__half2*)&r0.x);
                    p1 = __half22float2(*(__half2*)&r0.y);
                }
                ax += w * p0.x; ay += w * p0.y; az += w * p1.x; aw += w * p1.y;
            }
        }
        float4 b0 = make_float4(0.f, 0.f, 0.f, 0.f);
        if (bias) b0 = *(const float4*)(bias + o0);
        float rx = ax + b0.x, ry = ay + b0.y, rz = az + b0.z, rw = aw + b0.w;
        if (relu) {
            rx = fmaxf(rx, 0.f); ry = fmaxf(ry, 0.f);
            rz = fmaxf(rz, 0.f); rw = fmaxf(rw, 0.f);
        }
        if (OUTF) {
            *(float4*)((float*)Optr + (size_t)n * stride + o0) = make_float4(rx, ry, rz, rw);
        } else {
            __half2 p0 = __floats2half2_rn(rx, ry);
            __half2 p1 = __floats2half2_rn(rz, rw);
            uint2 o; o.x = *(unsigned*)&p0; o.y = *(unsigned*)&p1;
            *(uint2*)((__half*)Optr + (size_t)n * stride + o0) = o;
        }
    } else { // CW == 64, half input only
        int o0 = lane * 2;
        const __half* Th = (const __half*)Tptr;
        unsigned raw = *(const unsigned*)(Th + (size_t)n * stride + o0);
        float2 f0 = __half22float2(*(__half2*)&raw);
        float ax = f0.x * dn2, ay = f0.y * dn2;
        for (int base = s; base < e; base += 32) {
            int rem = e - base;
            int2 cw = make_int2(0, 0);
            if (lane < rem) cw = g_cw[base + lane];
            int nt = rem < 32 ? rem : 32;
            int t = 0;
            for (; t + 4 <= nt; t += 4) {
                int u0 = __shfl_sync(0xffffffffu, cw.x, t);
                int u1 = __shfl_sync(0xffffffffu, cw.x, t + 1);
                int u2 = __shfl_sync(0xffffffffu, cw.x, t + 2);
                int u3 = __shfl_sync(0xffffffffu, cw.x, t + 3);
                float w0 = __int_as_float(__shfl_sync(0xffffffffu, cw.y, t));
                float w1 = __int_as_float(__shfl_sync(0xffffffffu, cw.y, t + 1));
                float w2 = __int_as_float(__shfl_sync(0xffffffffu, cw.y, t + 2));
                float w3 = __int_as_float(__shfl_sync(0xffffffffu, cw.y, t + 3));
                unsigned r0 = *(const unsigned*)(Th + (size_t)u0 * stride + o0);
                unsigned r1 = *(const unsigned*)(Th + (size_t)u1 * stride + o0);
                unsigned r2 = *(const unsigned*)(Th + (size_t)u2 * stride + o0);
                unsigned r3 = *(const unsigned*)(Th + (size_t)u3 * stride + o0);
                float2 p0 = __half22float2(*(__half2*)&r0);
                float2 p1 = __half22float2(*(__half2*)&r1);
                float2 p2 = __half22float2(*(__half2*)&r2);
                float2 p3 = __half22float2(*(__half2*)&r3);
                ax += w0 * p0.x + w1 * p1.x + w2 * p2.x + w3 * p3.x;
                ay += w0 * p0.y + w1 * p1.y + w2 * p2.y + w3 * p3.y;
            }
            for (; t < nt; t++) {
                int u = __shfl_sync(0xffffffffu, cw.x, t);
                float w = __int_as_float(__shfl_sync(0xffffffffu, cw.y, t));
                unsigned r0 = *(const unsigned*)(Th + (size_t)u * stride + o0);
                float2 p0 = __half22float2(*(__half2*)&r0);
                ax += w * p0.x; ay += w * p0.y;
            }
        }
        float2 b0 = make_float2(0.f, 0.f);
        if (bias) b0 = *(const float2*)(bias + o0);
        float rx = ax + b0.x, ry = ay + b0.y;
        if (relu) { rx = fmaxf(rx, 0.f); ry = fmaxf(ry, 0.f); }
        if (OUTF) {
            *(float2*)((float*)Optr + (size_t)n * stride + o0) = make_float2(rx, ry);
        } else {
            __half2 p0 = __floats2half2_rn(rx, ry);
            *(unsigned*)((__half*)Optr + (size_t)n * stride + o0) = *(unsigned*)&p0;
        }
    }
}

// ---------------- pooling: run-length accumulate over 8 consecutive nodes ----------------
__global__ void k_pool(const float* __restrict__ h, const int* __restrict__ batch) {
    int idx = blockIdx.x * blockDim.x + threadIdx.x;
    if (idx >= (N_NODES / 8) * 16) return;
    int grp = idx >> 4, q = idx & 15;
    int n0 = grp * 8;
    float4 acc = make_float4(0.f, 0.f, 0.f, 0.f);
    int curg = batch[n0];
#pragma unroll
    for (int i = 0; i < 8; i++) {
        int n = n0 + i;
        int g = batch[n];
        float4 v = *(const float4*)(h + (size_t)n * 64 + q * 4);
        if (g != curg) {
            float* p = g_pool + curg * 64 + q * 4;
            atomicAdd(p + 0, acc.x); atomicAdd(p + 1, acc.y);
            atomicAdd(p + 2, acc.z); atomicAdd(p + 3, acc.w);
            acc = make_float4(0.f, 0.f, 0.f, 0.f);
            curg = g;
        }
        acc.x += v.x; acc.y += v.y; acc.z += v.z; acc.w += v.w;
    }
    float* p = g_pool + curg * 64 + q * 4;
    atomicAdd(p + 0, acc.x); atomicAdd(p + 1, acc.y);
    atomicAdd(p + 2, acc.z); atomicAdd(p + 3, acc.w);
}

// ---------------- counts via binary search over sorted batch ----------------
__global__ void k_cnt(const int* __restrict__ batch) {
    int g = blockIdx.x * blockDim.x + threadIdx.x;
    if (g >= N_GRAPHS) return;
    int lo = 0, hi = N_NODES;
    while (lo < hi) { int m = (lo + hi) >> 1; if (batch[m] < g) lo = m + 1; else hi = m; }
    int a = lo;
    lo = a; hi = N_NODES;
    while (lo < hi) { int m = (lo + hi) >> 1; if (batch[m] < g + 1) lo = m + 1; else hi = m; }
    g_cnt[g] = lo - a;
}

// ---------------- head ----------------
__global__ void k_final(const float* __restrict__ Wlin, const float* __restrict__ blin,
                        float* __restrict__ out) {
    int g = blockIdx.x;
    int t = threadIdx.x;  // 64 threads
    __shared__ float mean[64];
    __shared__ float logits[10];
    __shared__ float red2[2];
    float c = (float)g_cnt[g];
    float inv = 1.0f / fmaxf(c, 1.0f);
    mean[t] = g_pool[g * 64 + t] * inv;
    __syncthreads();
    if (t < 10) {
        float s = blin[t];
        for (int k = 0; k < 64; k++) s += mean[k] * Wlin[k * 10 + t];
        logits[t] = s;
    }
    __syncthreads();
    if (t == 0) {
        float mx = logits[0];
        for (int l = 1; l < 10; l++) mx = fmaxf(mx, logits[l]);
        float se = 0.f;
        for (int l = 0; l < 10; l++) se += expf(logits[l] - mx);
        red2[0] = mx;
        red2[1] = se;
    }
    __syncthreads();
    if (t < 10) {
        float lsm = logits[t] - red2[0] - logf(red2[1]);
        out[g * 10 + t] = lsm;
        out[N_GRAPHS * 10 + g * 10 + t] = expf(lsm);
    }
}

// ---------------- launch ----------------
extern "C" void kernel_launch(void* const* d_in, const int* in_sizes, int n_in,
                              void* d_out, int out_size) {
    const float* x     = (const float*)d_in[0];
    const int*   ei    = (const int*)d_in[1];
    const int*   batch = (const int*)d_in[2];
    const float* W1 = (const float*)d_in[4];  const float* b1 = (const float*)d_in[5];
    const float* W2 = (const float*)d_in[6];  const float* b2 = (const float*)d_in[7];
    const float* W3 = (const float*)d_in[8];  const float* b3 = (const float*)d_in[9];
    const float* W4 = (const float*)d_in[10]; const float* b4 = (const float*)d_in[11];
    const float* W5 = (const float*)d_in[12]; const float* b5 = (const float*)d_in[13];
    const float* W6 = (const float*)d_in[14]; const float* b6 = (const float*)d_in[15];
    const float* Wlin = (const float*)d_in[16];
    const float* blin = (const float*)d_in[17];
    const int* src = ei;
    const int* dst = ei + N_EDGES;
    float* out = (float*)d_out;

    __half *hA, *hB, *Wh;
    unsigned char *q8;
    float *h6;
    cudaGetSymbolAddress((void**)&hA, g_hA);
    cudaGetSymbolAddress((void**)&hB, g_hB);
    cudaGetSymbolAddress((void**)&q8, g_q8);
    cudaGetSymbolAddress((void**)&h6, g_h6);
    cudaGetSymbolAddress((void**)&Wh, g_Wh);

    const int TB = 256;
    int gN = (N_NODES + TB - 1) / TB;
    int gE = (N_EDGES + TB - 1) / TB;

    // preprocessing (+ converts)
    k_init<<<gN, TB>>>();
    k_tohalf<<<(N_NODES * 32 + TB - 1) / TB, TB>>>(x);
    k_wconv_all<<<(110592 + TB - 1) / TB, TB>>>(W1, W2, W3, W4, W5, W6);
    k_hist<<<gE, TB>>>(dst);
    k_scan1<<<NBLK, 1024>>>();
    k_scan2<<<1, 128>>>();
    k_scan3<<<NBLK, 1024>>>();
    k_fill<<<gE, TB>>>(src, dst);
    k_cnt<<<2, 256>>>(batch);

    int aggBlocks = N_NODES / 8;
    dim3 g256(4, 782), g128(2, 782), g64(1, 782);

    // L1: aggregate-first (128 ch, half) then GEMM 128->256 (+bias+relu)
    k_agg<128, false, false><<<aggBlocks, 256>>>(hA, hB, nullptr, 0, 128);
    k_gemm<<<g256, 256>>>(hB, Wh + OFF_W1, hA, 128, 256, b1, 1, 0);
    // L2: GEMM -> fp8, SINGLE-PASS 256-wide fp8 agg -> half
    k_gemm<<<g256, 256>>>(hA, Wh + OFF_W2, q8, 256, 256, nullptr, 0, 1);
    k_agg<256, false, true><<<aggBlocks, 256>>>(q8, hA, b2, 1, 256);
    // L3
    k_gemm<<<g256, 256>>>(hA, Wh + OFF_W3, q8, 256, 256, nullptr, 0, 1);
    k_agg<256, false, true><<<aggBlocks, 256>>>(q8, hA, b3, 1, 256);
    // L4: 256->128, fp8 agg input (1 line/gather)
    k_gemm<<<g128, 256>>>(hA, Wh + OFF_W4, q8, 256, 128, nullptr, 0, 1);
    k_agg<128, false, true><<<aggBlocks, 256>>>(q8, hA, b4, 1, 128);
    // L5: 128->128, fp8
    k_gemm<<<g128, 256>>>(hA, Wh + OFF_W5, q8, 128, 128, nullptr, 0, 1);
    k_agg<128, false, true><<<aggBlocks, 256>>>(q8, hA, b5, 1, 128);
    // L6: 128->64, no relu; half path; agg writes fp32 for pooling
    k_gemm<<<g64, 256>>>(hA, Wh + OFF_W6, hB, 128, 64, nullptr, 0, 0);
    k_agg<64, true, false><<<aggBlocks, 256>>>(hB, h6, b6, 0, 64);

    // pooling + head
    k_pool<<<((N_NODES / 8) * 16 + TB - 1) / TB, TB>>>(h6, batch);
    k_final<<<N_GRAPHS, 64>>>(Wlin, blin, out);
}

// round 17
// speedup vs baseline: 1.3291x; 1.1192x over previous
#include <cuda_runtime.h>
#include <cuda_fp16.h>
#include <mma.h>
#include <math.h>

using namespace nvcuda;

#define N_NODES  100000
#define N_EDGES  3200000
#define N_GRAPHS 512
#define NBLK     98          // ceil(100000/1024)

// ---------------- scratch (static device globals; no allocation) ----------------
__device__ __half g_hA[(size_t)N_NODES * 256];
__device__ __half g_hB[(size_t)N_NODES * 256];
__device__ unsigned char g_q8[(size_t)N_NODES * 256];  // fp8 e4m3 activations
__device__ float  g_h6[(size_t)N_NODES * 64];   // final layer output (fp32 for pooling)
__device__ __half g_Wh[262144];                 // all W matrices in half (offsets below)
__device__ int    g_deg[N_NODES];
__device__ float  g_dinv[N_NODES];
__device__ int    g_rowptr[N_NODES + 1];
__device__ int    g_cursor[N_NODES];
__device__ int2   g_cw[N_EDGES];                // packed (src, half2(w,w))
__device__ int    g_bsum[128];
__device__ float  g_pool[N_GRAPHS * 64];
__device__ int    g_cnt[N_GRAPHS];

// W offsets in g_Wh (half elements)
#define OFF_W1 0           // 128*256 = 32768
#define OFF_W2 32768       // 256*256 = 65536
#define OFF_W3 98304       // 65536
#define OFF_W4 163840      // 256*128 = 32768
#define OFF_W5 196608      // 128*128 = 16384
#define OFF_W6 212992      // 128*64  = 8192

// ---------------- fp8 helpers ----------------
__device__ __forceinline__ unsigned short f8pack(float lo, float hi) {
    unsigned short r;
    asm("cvt.rn.satfinite.e4m3x2.f32 %0, %1, %2;" : "=h"(r) : "f"(hi), "f"(lo));
    return r;
}
// e4m3x2 (16 bits) -> f16x2
__device__ __forceinline__ __half2 f8x2_to_h2(unsigned short s) {
    unsigned r;
    asm("cvt.rn.f16x2.e4m3x2 %0, %1;" : "=r"(r) : "h"(s));
    return *(__half2*)&r;
}
__device__ __forceinline__ void f8x4_to_f(unsigned v, float2& a, float2& b) {
    a = __half22float2(f8x2_to_h2((unsigned short)(v & 0xffffu)));
    b = __half22float2(f8x2_to_h2((unsigned short)(v >> 16)));
}

// ---------------- init ----------------
__global__ void k_init() {
    int i = blockIdx.x * blockDim.x + threadIdx.x;
    if (i < N_NODES) g_deg[i] = 1;               // self loop
    if (i < N_GRAPHS * 64) g_pool[i] = 0.f;
}

// ---------------- fp32 -> half converts ----------------
__global__ void k_tohalf(const float* __restrict__ x) {
    int i = blockIdx.x * blockDim.x + threadIdx.x;   // one float4 -> 4 halves
    if (i >= N_NODES * 32) return;
    float4 v = *(const float4*)(x + (size_t)i * 4);
    __half2 h0 = __floats2half2_rn(v.x, v.y);
    __half2 h1 = __floats2half2_rn(v.z, v.w);
    uint2 o; o.x = *(unsigned*)&h0; o.y = *(unsigned*)&h1;
    *(uint2*)(g_hA + (size_t)i * 4) = o;
}

// all six W matrices in one kernel; i indexes half2 pairs (110592 total)
__global__ void k_wconv_all(const float* __restrict__ W1, const float* __restrict__ W2,
                            const float* __restrict__ W3, const float* __restrict__ W4,
                            const float* __restrict__ W5, const float* __restrict__ W6) {
    int i = blockIdx.x * blockDim.x + threadIdx.x;
    if (i >= 110592) return;
    const float* src;
    int off, loc;
    if (i < 16384)       { src = W1; off = OFF_W1; loc = i; }
    else if (i < 49152)  { src = W2; off = OFF_W2; loc = i - 16384; }
    else if (i < 81920)  { src = W3; off = OFF_W3; loc = i - 49152; }
    else if (i < 98304)  { src = W4; off = OFF_W4; loc = i - 81920; }
    else if (i < 106496) { src = W5; off = OFF_W5; loc = i - 98304; }
    else                 { src = W6; off = OFF_W6; loc = i - 106496; }
    float2 v = *(const float2*)(src + loc * 2);
    __half2 h = __floats2half2_rn(v.x, v.y);
    *(unsigned*)(g_Wh + off + loc * 2) = *(unsigned*)&h;
}

// ---------------- degree histogram over dst ----------------
__global__ void k_hist(const int* __restrict__ dst) {
    int i = blockIdx.x * blockDim.x + threadIdx.x;
    if (i < N_EDGES) atomicAdd(&g_deg[dst[i]], 1);
}

// ---------------- 3-phase multi-block exclusive scan of (deg-1) ----------------
__global__ void k_scan1() {
    __shared__ int ws[32];
    int t = threadIdx.x;
    int i = blockIdx.x * 1024 + t;
    int v = (i < N_NODES) ? (g_deg[i] - 1) : 0;
    int lane = t & 31, wid = t >> 5;
    int x = v;
#pragma unroll
    for (int off = 1; off < 32; off <<= 1) {
        int y = __shfl_up_sync(0xffffffffu, x, off);
        if (lane >= off) x += y;
    }
    if (lane == 31) ws[wid] = x;
    __syncthreads();
    if (wid == 0) {
        int s = ws[lane];
#pragma unroll
        for (int off = 1; off < 32; off <<= 1) {
            int y = __shfl_up_sync(0xffffffffu, s, off);
            if (lane >= off) s += y;
        }
        ws[lane] = s;
    }
    __syncthreads();
    int excl = (wid ? ws[wid - 1] : 0) + (x - v);
    if (i < N_NODES) g_rowptr[i] = excl;
    if (t == 0) g_bsum[blockIdx.x] = ws[31];
}

__global__ void k_scan2() {
    __shared__ int ws[4];
    int t = threadIdx.x;
    int v = (t < NBLK) ? g_bsum[t] : 0;
    int lane = t & 31, wid = t >> 5;
    int x = v;
#pragma unroll
    for (int off = 1; off < 32; off <<= 1) {
        int y = __shfl_up_sync(0xffffffffu, x, off);
        if (lane >= off) x += y;
    }
    if (lane == 31) ws[wid] = x;
    __syncthreads();
    int add = 0;
    for (int w = 0; w < wid; w++) add += ws[w];
    if (t < NBLK) g_bsum[t] = add + x - v;
}

__global__ void k_scan3() {
    int i = blockIdx.x * 1024 + threadIdx.x;
    if (i < N_NODES) {
        int v = g_rowptr[i] + g_bsum[blockIdx.x];
        g_rowptr[i] = v;
        g_cursor[i] = v;
        g_dinv[i] = rsqrtf((float)g_deg[i]);
    }
    if (i == 0) g_rowptr[N_NODES] = N_EDGES;
}

// fill CSR with packed (src, half2(w,w)), w = dinv[src]*dinv[dst]
__global__ void k_fill(const int* __restrict__ src, const int* __restrict__ dst) {
    int i = blockIdx.x * blockDim.x + threadIdx.x;
    if (i < N_EDGES) {
        int d = dst[i];
        int s = src[i];
        float w = g_dinv[s] * g_dinv[d];
        __half2 wh = __floats2half2_rn(w, w);
        int p = atomicAdd(&g_cursor[d], 1);
        g_cw[p] = make_int2(s, *(int*)&wh);
    }
}

// ---------------- wmma GEMM: Out = A(half) @ Wh(half) + bias, relu; out half or fp8 ----------------
__global__ __launch_bounds__(256) void k_gemm(const __half* __restrict__ A,
                                              const __half* __restrict__ W,
                                              void* __restrict__ Out,
                                              int K, int Cn,
                                              const float* __restrict__ bias, int relu,
                                              int out_fp8) {
    __shared__ __half As[128][24];
    __shared__ __half Ws[16][72];
    __shared__ float  stage[8][1024];

    int tid = threadIdx.x;
    int wid = tid >> 5, lane = tid & 31;
    int wr = wid & 3, wc = wid >> 2;
    int row0 = blockIdx.y * 128, col0 = blockIdx.x * 64;

    wmma::fragment<wmma::accumulator, 16, 16, 16, float> fc[2][2];
#pragma unroll
    for (int i = 0; i < 2; i++)
#pragma unroll
        for (int j = 0; j < 2; j++) wmma::fill_fragment(fc[i][j], 0.f);

    int lr = tid >> 1, lp = tid & 1;
    int grow = row0 + lr;
    bool av = grow < N_NODES;
    const __half* Ap = A + (size_t)(av ? grow : 0) * K + lp * 8;

    for (int kk = 0; kk < K; kk += 16) {
        uint4 v = make_uint4(0u, 0u, 0u, 0u);
        if (av) v = *(const uint4*)(Ap + kk);
        *(uint4*)&As[lr][lp * 8] = v;
        if (tid < 128) {
            int r = tid >> 3, p = tid & 7;
            *(uint4*)&Ws[r][p * 8] =
                *(const uint4*)(W + (size_t)(kk + r) * Cn + col0 + p * 8);
        }
        __syncthreads();
        wmma::fragment<wmma::matrix_a, 16, 16, 16, __half, wmma::row_major> fa[2];
        wmma::fragment<wmma::matrix_b, 16, 16, 16, __half, wmma::row_major> fb[2];
        wmma::load_matrix_sync(fa[0], &As[wr * 32][0], 24);
        wmma::load_matrix_sync(fa[1], &As[wr * 32 + 16][0], 24);
        wmma::load_matrix_sync(fb[0], &Ws[0][wc * 32], 72);
        wmma::load_matrix_sync(fb[1], &Ws[0][wc * 32 + 16], 72);
#pragma unroll
        for (int i = 0; i < 2; i++)
#pragma unroll
            for (int j = 0; j < 2; j++)
                wmma::mma_sync(fc[i][j], fa[i], fb[j], fc[i][j]);
        __syncthreads();
    }

#pragma unroll
    for (int i = 0; i < 2; i++)
#pragma unroll
        for (int j = 0; j < 2; j++)
            wmma::store_matrix_sync(&stage[wid][(i * 16) * 32 + j * 16], fc[i][j], 32,
                                    wmma::mem_row_major);
    __syncwarp();

    int gr = row0 + wr * 32 + lane;
    if (gr < N_NODES) {
        int gc0 = col0 + wc * 32;
        const float* srow = &stage[wid][lane * 32];
#pragma unroll
        for (int q = 0; q < 4; q++) {
            float4 f0 = *(const float4*)(srow + q * 8);
            float4 f1 = *(const float4*)(srow + q * 8 + 4);
            float b[8] = {0, 0, 0, 0, 0, 0, 0, 0};
            if (bias) {
                float4 bb0 = *(const float4*)(bias + gc0 + q * 8);
                float4 bb1 = *(const float4*)(bias + gc0 + q * 8 + 4);
                b[0] = bb0.x; b[1] = bb0.y; b[2] = bb0.z; b[3] = bb0.w;
                b[4] = bb1.x; b[5] = bb1.y; b[6] = bb1.z; b[7] = bb1.w;
            }
            float r[8] = {f0.x + b[0], f0.y + b[1], f0.z + b[2], f0.w + b[3],
                          f1.x + b[4], f1.y + b[5], f1.z + b[6], f1.w + b[7]};
            if (relu) {
#pragma unroll
                for (int q2 = 0; q2 < 8; q2++) r[q2] = fmaxf(r[q2], 0.f);
            }
            if (out_fp8) {
                unsigned short s0 = f8pack(r[0], r[1]);
                unsigned short s1 = f8pack(r[2], r[3]);
                unsigned short s2 = f8pack(r[4], r[5]);
                unsigned short s3 = f8pack(r[6], r[7]);
                uint2 o;
                o.x = (unsigned)s0 | ((unsigned)s1 << 16);
                o.y = (unsigned)s2 | ((unsigned)s3 << 16);
                *(uint2*)((unsigned char*)Out + (size_t)gr * Cn + gc0 + q * 8) = o;
            } else {
                __half2 h0 = __floats2half2_rn(r[0], r[1]);
                __half2 h1 = __floats2half2_rn(r[2], r[3]);
                __half2 h2 = __floats2half2_rn(r[4], r[5]);
                __half2 h3 = __floats2half2_rn(r[6], r[7]);
                uint4 o;
                o.x = *(unsigned*)&h0; o.y = *(unsigned*)&h1;
                o.z = *(unsigned*)&h2; o.w = *(unsigned*)&h3;
                *(uint4*)((__half*)Out + (size_t)gr * Cn + gc0 + q * 8) = o;
            }
        }
    }
}

// ---------------- CSR aggregation: HFMA2 half2 accumulation ----------------
// CW=256: fp8, full width one pass (8B/lane). CW=128: fp8 4B/lane or half 8B/lane. CW=64: half.
template <int CW, bool OUTF, bool IN8>
__global__ void k_agg(const void* __restrict__ Tptr, void* __restrict__ Optr,
                      const float* __restrict__ bias, int relu, int stride) {
    int warp = threadIdx.x >> 5;
    int lane = threadIdx.x & 31;
    int n = blockIdx.x * 8 + warp;
    float dn = g_dinv[n];
    float dn2 = dn * dn;
    int s = g_rowptr[n], e = g_rowptr[n + 1];

    if (CW == 256) {   // fp8 input, 8 channels/lane
        int o0 = lane * 8;   // bytes
        const unsigned char* T8 = (const unsigned char*)Tptr;
        uint2 sraw = *(const uint2*)(T8 + (size_t)n * stride + o0);
        float2 sf0, sf1, sf2, sf3;
        f8x4_to_f(sraw.x, sf0, sf1);
        f8x4_to_f(sraw.y, sf2, sf3);

        __half2 acc0 = __float2half2_rn(0.f), acc1 = acc0, acc2 = acc0, acc3 = acc0;
        for (int base = s; base < e; base += 32) {
            int rem = e - base;
            int2 cw = make_int2(0, 0);
            if (lane < rem) cw = g_cw[base + lane];
            int nt = rem < 32 ? rem : 32;
            int t = 0;
            for (; t + 4 <= nt; t += 4) {
                int u0 = __shfl_sync(0xffffffffu, cw.x, t);
                int u1 = __shfl_sync(0xffffffffu, cw.x, t + 1);
                int u2 = __shfl_sync(0xffffffffu, cw.x, t + 2);
                int u3 = __shfl_sync(0xffffffffu, cw.x, t + 3);
                unsigned wb0 = __shfl_sync(0xffffffffu, cw.y, t);
                unsigned wb1 = __shfl_sync(0xffffffffu, cw.y, t + 1);
                unsigned wb2 = __shfl_sync(0xffffffffu, cw.y, t + 2);
                unsigned wb3 = __shfl_sync(0xffffffffu, cw.y, t + 3);
                uint2 r0 = *(const uint2*)(T8 + (size_t)u0 * stride + o0);
                uint2 r1 = *(const uint2*)(T8 + (size_t)u1 * stride + o0);
                uint2 r2 = *(const uint2*)(T8 + (size_t)u2 * stride + o0);
                uint2 r3 = *(const uint2*)(T8 + (size_t)u3 * stride + o0);
                __half2 w0 = *(__half2*)&wb0, w1 = *(__half2*)&wb1;
                __half2 w2 = *(__half2*)&wb2, w3 = *(__half2*)&wb3;
                acc0 = __hfma2(f8x2_to_h2((unsigned short)(r0.x & 0xffffu)), w0, acc0);
                acc1 = __hfma2(f8x2_to_h2((unsigned short)(r0.x >> 16)), w0, acc1);
                acc2 = __hfma2(f8x2_to_h2((unsigned short)(r0.y & 0xffffu)), w0, acc2);
                acc3 = __hfma2(f8x2_to_h2((unsigned short)(r0.y >> 16)), w0, acc3);
                acc0 = __hfma2(f8x2_to_h2((unsigned short)(r1.x & 0xffffu)), w1, acc0);
                acc1 = __hfma2(f8x2_to_h2((unsigned short)(r1.x >> 16)), w1, acc1);
                acc2 = __hfma2(f8x2_to_h2((unsigned short)(r1.y & 0xffffu)), w1, acc2);
                acc3 = __hfma2(f8x2_to_h2((unsigned short)(r1.y >> 16)), w1, acc3);
                acc0 = __hfma2(f8x2_to_h2((unsigned short)(r2.x & 0xffffu)), w2, acc0);
                acc1 = __hfma2(f8x2_to_h2((unsigned short)(r2.x >> 16)), w2, acc1);
                acc2 = __hfma2(f8x2_to_h2((unsigned short)(r2.y & 0xffffu)), w2, acc2);
                acc3 = __hfma2(f8x2_to_h2((unsigned short)(r2.y >> 16)), w2, acc3);
                acc0 = __hfma2(f8x2_to_h2((unsigned short)(r3.x & 0xffffu)), w3, acc0);
                acc1 = __hfma2(f8x2_to_h2((unsigned short)(r3.x >> 16)), w3, acc1);
                acc2 = __hfma2(f8x2_to_h2((unsigned short)(r3.y & 0xffffu)), w3, acc2);
                acc3 = __hfma2(f8x2_to_h2((unsigned short)(r3.y >> 16)), w3, acc3);
            }
            for (; t < nt; t++) {
                int u = __shfl_sync(0xffffffffu, cw.x, t);
                unsigned wb = __shfl_sync(0xffffffffu, cw.y, t);
                uint2 r0 = *(const uint2*)(T8 + (size_t)u * stride + o0);
                __half2 w = *(__half2*)&wb;
                acc0 = __hfma2(f8x2_to_h2((unsigned short)(r0.x & 0xffffu)), w, acc0);
                acc1 = __hfma2(f8x2_to_h2((unsigned short)(r0.x >> 16)), w, acc1);
                acc2 = __hfma2(f8x2_to_h2((unsigned short)(r0.y & 0xffffu)), w, acc2);
                acc3 = __hfma2(f8x2_to_h2((unsigned short)(r0.y >> 16)), w, acc3);
            }
        }
        float2 a0 = __half22float2(acc0), a1 = __half22float2(acc1);
        float2 a2 = __half22float2(acc2), a3 = __half22float2(acc3);
        float r[8] = {a0.x + sf0.x * dn2, a0.y + sf0.y * dn2,
                      a1.x + sf1.x * dn2, a1.y + sf1.y * dn2,
                      a2.x + sf2.x * dn2, a2.y + sf2.y * dn2,
                      a3.x + sf3.x * dn2, a3.y + sf3.y * dn2};
        if (bias) {
            float4 b0 = *(const float4*)(bias + o0);
            float4 b1 = *(const float4*)(bias + o0 + 4);
            r[0] += b0.x; r[1] += b0.y; r[2] += b0.z; r[3] += b0.w;
            r[4] += b1.x; r[5] += b1.y; r[6] += b1.z; r[7] += b1.w;
        }
        if (relu) {
#pragma unroll
            for (int q = 0; q < 8; q++) r[q] = fmaxf(r[q], 0.f);
        }
        __half2 h0 = __floats2half2_rn(r[0], r[1]);
        __half2 h1 = __floats2half2_rn(r[2], r[3]);
        __half2 h2 = __floats2half2_rn(r[4], r[5]);
        __half2 h3 = __floats2half2_rn(r[6], r[7]);
        uint4 o;
        o.x = *(unsigned*)&h0; o.y = *(unsigned*)&h1;
        o.z = *(unsigned*)&h2; o.w = *(unsigned*)&h3;
        *(uint4*)((__half*)Optr + (size_t)n * stride + o0) = o;
    } else if (CW == 128) {
        const __half* Th = (const __half*)Tptr;
        const unsigned char* T8 = (const unsigned char*)Tptr;
        int o0 = lane * 4;   // elements (fp8: bytes; half: halves index scaled below)
        float2 sf0, sf1;
        if (IN8) {
            unsigned sraw = *(const unsigned*)(T8 + (size_t)n * stride + o0);
            f8x4_to_f(sraw, sf0, sf1);
        } else {
            uint2 sraw = *(const uint2*)(Th + (size_t)n * stride + o0);
            sf0 = __half22float2(*(__half2*)&sraw.x);
            sf1 = __half22float2(*(__half2*)&sraw.y);
        }
        __half2 acc0 = __float2half2_rn(0.f), acc1 = acc0;
        for (int base = s; base < e; base += 32) {
            int rem = e - base;
            int2 cw = make_int2(0, 0);
            if (lane < rem) cw = g_cw[base + lane];
            int nt = rem < 32 ? rem : 32;
            int t = 0;
            for (; t + 4 <= nt; t += 4) {
                int u0 = __shfl_sync(0xffffffffu, cw.x, t);
                int u1 = __shfl_sync(0xffffffffu, cw.x, t + 1);
                int u2 = __shfl_sync(0xffffffffu, cw.x, t + 2);
                int u3 = __shfl_sync(0xffffffffu, cw.x, t + 3);
                unsigned wb0 = __shfl_sync(0xffffffffu, cw.y, t);
                unsigned wb1 = __shfl_sync(0xffffffffu, cw.y, t + 1);
                unsigned wb2 = __shfl_sync(0xffffffffu, cw.y, t + 2);
                unsigned wb3 = __shfl_sync(0xffffffffu, cw.y, t + 3);
                __half2 w0 = *(__half2*)&wb0, w1 = *(__half2*)&wb1;
                __half2 w2 = *(__half2*)&wb2, w3 = *(__half2*)&wb3;
                if (IN8) {
                    unsigned r0 = *(const unsigned*)(T8 + (size_t)u0 * stride + o0);
                    unsigned r1 = *(const unsigned*)(T8 + (size_t)u1 * stride + o0);
                    unsigned r2 = *(const unsigned*)(T8 + (size_t)u2 * stride + o0);
                    unsigned r3 = *(const unsigned*)(T8 + (size_t)u3 * stride + o0);
                    acc0 = __hfma2(f8x2_to_h2((unsigned short)(r0 & 0xffffu)), w0, acc0);
                    acc1 = __hfma2(f8x2_to_h2((unsigned short)(r0 >> 16)), w0, acc1);
                    acc0 = __hfma2(f8x2_to_h2((unsigned short)(r1 & 0xffffu)), w1, acc0);
                    acc1 = __hfma2(f8x2_to_h2((unsigned short)(r1 >> 16)), w1, acc1);
                    acc0 = __hfma2(f8x2_to_h2((unsigned short)(r2 & 0xffffu)), w2, acc0);
                    acc1 = __hfma2(f8x2_to_h2((unsigned short)(r2 >> 16)), w2, acc1);
                    acc0 = __hfma2(f8x2_to_h2((unsigned short)(r3 & 0xffffu)), w3, acc0);
                    acc1 = __hfma2(f8x2_to_h2((unsigned short)(r3 >> 16)), w3, acc1);
                } else {
                    uint2 r0 = *(const uint2*)(Th + (size_t)u0 * stride + o0);
                    uint2 r1 = *(const uint2*)(Th + (size_t)u1 * stride + o0);
                    uint2 r2 = *(const uint2*)(Th + (size_t)u2 * stride + o0);
                    uint2 r3 = *(const uint2*)(Th + (size_t)u3 * stride + o0);
                    acc0 = __hfma2(*(__half2*)&r0.x, w0, acc0);
                    acc1 = __hfma2(*(__half2*)&r0.y, w0, acc1);
                    acc0 = __hfma2(*(__half2*)&r1.x, w1, acc0);
                    acc1 = __hfma2(*(__half2*)&r1.y, w1, acc1);
                    acc0 = __hfma2(*(__half2*)&r2.x, w2, acc0);
                    acc1 = __hfma2(*(__half2*)&r2.y, w2, acc1);
                    acc0 = __hfma2(*(__half2*)&r3.x, w3, acc0);
                    acc1 = __hfma2(*(__half2*)&r3.y, w3, acc1);
                }
            }
            for (; t < nt; t++) {
                int u = __shfl_sync(0xffffffffu, cw.x, t);
                unsigned wb = __shfl_sync(0xffffffffu, cw.y, t);
                __half2 w = *(__half2*)&wb;
                if (IN8) {
                    unsigned r0 = *(const unsigned*)(T8 + (size_t)u * stride + o0);
                    acc0 = __hfma2(f8x2_to_h2((unsigned short)(r0 & 0xffffu)), w, acc0);
                    acc1 = __hfma2(f8x2_to_h2((unsigned short)(r0 >> 16)), w, acc1);
                } else {
                    uint2 r0 = *(const uint2*)(Th + (size_t)u * stride + o0);
                    acc0 = __hfma2(*(__half2*)&r0.x, w, acc0);
                    acc1 = __hfma2(*(__half2*)&r0.y, w, acc1);
                }
            }
        }
        float2 a0 = __half22float2(acc0), a1 = __half22float2(acc1);
        float rx = a0.x + sf0.x * dn2, ry = a0.y + sf0.y * dn2;
        float rz = a1.x + sf1.x * dn2, rw = a1.y + sf1.y * dn2;
        if (bias) {
            float4 b0 = *(const float4*)(bias + o0);
            rx += b0.x; ry += b0.y; rz += b0.z; rw += b0.w;
        }
        if (relu) {
            rx = fmaxf(rx, 0.f); ry = fmaxf(ry, 0.f);
            rz = fmaxf(rz, 0.f); rw = fmaxf(rw, 0.f);
        }
        if (OUTF) {
            *(float4*)((float*)Optr + (size_t)n * stride + o0) = make_float4(rx, ry, rz, rw);
        } else {
            __half2 p0 = __floats2half2_rn(rx, ry);
            __half2 p1 = __floats2half2_rn(rz, rw);
            uint2 o; o.x = *(unsigned*)&p0; o.y = *(unsigned*)&p1;
            *(uint2*)((__half*)Optr + (size_t)n * stride + o0) = o;
        }
    } else { // CW == 64, half input
        int o0 = lane * 2;
        const __half* Th = (const __half*)Tptr;
        unsigned sraw = *(const unsigned*)(Th + (size_t)n * stride + o0);
        float2 sf0 = __half22float2(*(__half2*)&sraw);
        __half2 acc0 = __float2half2_rn(0.f);
        for (int base = s; base < e; base += 32) {
            int rem = e - base;
            int2 cw = make_int2(0, 0);
            if (lane < rem) cw = g_cw[base + lane];
            int nt = rem < 32 ? rem : 32;
            int t = 0;
            for (; t + 4 <= nt; t += 4) {
                int u0 = __shfl_sync(0xffffffffu, cw.x, t);
                int u1 = __shfl_sync(0xffffffffu, cw.x, t + 1);
                int u2 = __shfl_sync(0xffffffffu, cw.x, t + 2);
                int u3 = __shfl_sync(0xffffffffu, cw.x, t + 3);
                unsigned wb0 = __shfl_sync(0xffffffffu, cw.y, t);
                unsigned wb1 = __shfl_sync(0xffffffffu, cw.y, t + 1);
                unsigned wb2 = __shfl_sync(0xffffffffu, cw.y, t + 2);
                unsigned wb3 = __shfl_sync(0xffffffffu, cw.y, t + 3);
                unsigned r0 = *(const unsigned*)(Th + (size_t)u0 * stride + o0);
                unsigned r1 = *(const unsigned*)(Th + (size_t)u1 * stride + o0);
                unsigned r2 = *(const unsigned*)(Th + (size_t)u2 * stride + o0);
                unsigned r3 = *(const unsigned*)(Th + (size_t)u3 * stride + o0);
                acc0 = __hfma2(*(__half2*)&r0, *(__half2*)&wb0, acc0);
                acc0 = __hfma2(*(__half2*)&r1, *(__half2*)&wb1, acc0);
                acc0 = __hfma2(*(__half2*)&r2, *(__half2*)&wb2, acc0);
                acc0 = __hfma2(*(__half2*)&r3, *(__half2*)&wb3, acc0);
            }
            for (; t < nt; t++) {
                int u = __shfl_sync(0xffffffffu, cw.x, t);
                unsigned wb = __shfl_sync(0xffffffffu, cw.y, t);
                unsigned r0 = *(const unsigned*)(Th + (size_t)u * stride + o0);
                acc0 = __hfma2(*(__half2*)&r0, *(__half2*)&wb, acc0);
            }
        }
        float2 a0 = __half22float2(acc0);
        float rx = a0.x + sf0.x * dn2, ry = a0.y + sf0.y * dn2;
        if (bias) {
            float2 b0 = *(const float2*)(bias + o0);
            rx += b0.x; ry += b0.y;
        }
        if (relu) { rx = fmaxf(rx, 0.f); ry = fmaxf(ry, 0.f); }
        if (OUTF) {
            *(float2*)((float*)Optr + (size_t)n * stride + o0) = make_float2(rx, ry);
        } else {
            __half2 p0 = __floats2half2_rn(rx, ry);
            *(unsigned*)((__half*)Optr + (size_t)n * stride + o0) = *(unsigned*)&p0;
        }
    }
}

// ---------------- pooling: run-length accumulate over 8 consecutive nodes ----------------
__global__ void k_pool(const float* __restrict__ h, const int* __restrict__ batch) {
    int idx = blockIdx.x * blockDim.x + threadIdx.x;
    if (idx >= (N_NODES / 8) * 16) return;
    int grp = idx >> 4, q = idx & 15;
    int n0 = grp * 8;
    float4 acc = make_float4(0.f, 0.f, 0.f, 0.f);
    int curg = batch[n0];
#pragma unroll
    for (int i = 0; i < 8; i++) {
        int n = n0 + i;
        int g = batch[n];
        float4 v = *(const float4*)(h + (size_t)n * 64 + q * 4);
        if (g != curg) {
            float* p = g_pool + curg * 64 + q * 4;
            atomicAdd(p + 0, acc.x); atomicAdd(p + 1, acc.y);
            atomicAdd(p + 2, acc.z); atomicAdd(p + 3, acc.w);
            acc = make_float4(0.f, 0.f, 0.f, 0.f);
            curg = g;
        }
        acc.x += v.x; acc.y += v.y; acc.z += v.z; acc.w += v.w;
    }
    float* p = g_pool + curg * 64 + q * 4;
    atomicAdd(p + 0, acc.x); atomicAdd(p + 1, acc.y);
    atomicAdd(p + 2, acc.z); atomicAdd(p + 3, acc.w);
}

// ---------------- counts via binary search over sorted batch ----------------
__global__ void k_cnt(const int* __restrict__ batch) {
    int g = blockIdx.x * blockDim.x + threadIdx.x;
    if (g >= N_GRAPHS) return;
    int lo = 0, hi = N_NODES;
    while (lo < hi) { int m = (lo + hi) >> 1; if (batch[m] < g) lo = m + 1; else hi = m; }
    int a = lo;
    lo = a; hi = N_NODES;
    while (lo < hi) { int m = (lo + hi) >> 1; if (batch[m] < g + 1) lo = m + 1; else hi = m; }
    g_cnt[g] = lo - a;
}

// ---------------- head ----------------
__global__ void k_final(const float* __restrict__ Wlin, const float* __restrict__ blin,
                        float* __restrict__ out) {
    int g = blockIdx.x;
    int t = threadIdx.x;  // 64 threads
    __shared__ float mean[64];
    __shared__ float logits[10];
    __shared__ float red2[2];
    float c = (float)g_cnt[g];
    float inv = 1.0f / fmaxf(c, 1.0f);
    mean[t] = g_pool[g * 64 + t] * inv;
    __syncthreads();
    if (t < 10) {
        float s = blin[t];
        for (int k = 0; k < 64; k++) s += mean[k] * Wlin[k * 10 + t];
        logits[t] = s;
    }
    __syncthreads();
    if (t == 0) {
        float mx = logits[0];
        for (int l = 1; l < 10; l++) mx = fmaxf(mx, logits[l]);
        float se = 0.f;
        for (int l = 0; l < 10; l++) se += expf(logits[l] - mx);
        red2[0] = mx;
        red2[1] = se;
    }
    __syncthreads();
    if (t < 10) {
        float lsm = logits[t] - red2[0] - logf(red2[1]);
        out[g * 10 + t] = lsm;
        out[N_GRAPHS * 10 + g * 10 + t] = expf(lsm);
    }
}

// ---------------- launch ----------------
extern "C" void kernel_launch(void* const* d_in, const int* in_sizes, int n_in,
                              void* d_out, int out_size) {
    const float* x     = (const float*)d_in[0];
    const int*   ei    = (const int*)d_in[1];
    const int*   batch = (const int*)d_in[2];
    const float* W1 = (const float*)d_in[4];  const float* b1 = (const float*)d_in[5];
    const float* W2 = (const float*)d_in[6];  const float* b2 = (const float*)d_in[7];
    const float* W3 = (const float*)d_in[8];  const float* b3 = (const float*)d_in[9];
    const float* W4 = (const float*)d_in[10]; const float* b4 = (const float*)d_in[11];
    const float* W5 = (const float*)d_in[12]; const float* b5 = (const float*)d_in[13];
    const float* W6 = (const float*)d_in[14]; const float* b6 = (const float*)d_in[15];
    const float* Wlin = (const float*)d_in[16];
    const float* blin = (const float*)d_in[17];
    const int* src = ei;
    const int* dst = ei + N_EDGES;
    float* out = (float*)d_out;

    __half *hA, *hB, *Wh;
    unsigned char *q8;
    float *h6;
    cudaGetSymbolAddress((void**)&hA, g_hA);
    cudaGetSymbolAddress((void**)&hB, g_hB);
    cudaGetSymbolAddress((void**)&q8, g_q8);
    cudaGetSymbolAddress((void**)&h6, g_h6);
    cudaGetSymbolAddress((void**)&Wh, g_Wh);

    const int TB = 256;
    int gN = (N_NODES + TB - 1) / TB;
    int gE = (N_EDGES + TB - 1) / TB;

    // preprocessing (+ converts)
    k_init<<<gN, TB>>>();
    k_tohalf<<<(N_NODES * 32 + TB - 1) / TB, TB>>>(x);
    k_wconv_all<<<(110592 + TB - 1) / TB, TB>>>(W1, W2, W3, W4, W5, W6);
    k_hist<<<gE, TB>>>(dst);
    k_scan1<<<NBLK, 1024>>>();
    k_scan2<<<1, 128>>>();
    k_scan3<<<NBLK, 1024>>>();
    k_fill<<<gE, TB>>>(src, dst);
    k_cnt<<<2, 256>>>(batch);

    int aggBlocks = N_NODES / 8;
    dim3 g256(4, 782), g128(2, 782), g64(1, 782);

    // L1: aggregate-first (128 ch, half) then GEMM 128->256 (+bias+relu)
    k_agg<128, false, false><<<aggBlocks, 256>>>(hA, hB, nullptr, 0, 128);
    k_gemm<<<g256, 256>>>(hB, Wh + OFF_W1, hA, 128, 256, b1, 1, 0);
    // L2: GEMM -> fp8, SINGLE-PASS 256-wide fp8 agg -> half
    k_gemm<<<g256, 256>>>(hA, Wh + OFF_W2, q8, 256, 256, nullptr, 0, 1);
    k_agg<256, false, true><<<aggBlocks, 256>>>(q8, hA, b2, 1, 256);
    // L3
    k_gemm<<<g256, 256>>>(hA, Wh + OFF_W3, q8, 256, 256, nullptr, 0, 1);
    k_agg<256, false, true><<<aggBlocks, 256>>>(q8, hA, b3, 1, 256);
    // L4: 256->128, fp8 agg input
    k_gemm<<<g128, 256>>>(hA, Wh + OFF_W4, q8, 256, 128, nullptr, 0, 1);
    k_agg<128, false, true><<<aggBlocks, 256>>>(q8, hA, b4, 1, 128);
    // L5: 128->128, fp8
    k_gemm<<<g128, 256>>>(hA, Wh + OFF_W5, q8, 128, 128, nullptr, 0, 1);
    k_agg<128, false, true><<<aggBlocks, 256>>>(q8, hA, b5, 1, 128);
    // L6: 128->64, no relu; half path; agg writes fp32 for pooling
    k_gemm<<<g64, 256>>>(hA, Wh + OFF_W6, hB, 128, 64, nullptr, 0, 0);
    k_agg<64, true, false><<<aggBlocks, 256>>>(hB, h6, b6, 0, 64);

    // pooling + head
    k_pool<<<((N_NODES / 8) * 16 + TB - 1) / TB, TB>>>(h6, batch);
    k_final<<<N_GRAPHS, 64>>>(Wlin, blin, out);
}